// round 1
// baseline (speedup 1.0000x reference)
#include <cuda_runtime.h>
#include <cuda_bf16.h>
#include <math_constants.h>

// Problem constants
#define BB 4
#define TT 2048
#define DD 768
#define HH 12
#define DHH 64
#define THREE_D 2304
#define MTOT (BB*TT)       // 8192

// Scratch (device globals — no allocation allowed)
__device__ float g_qkv[(size_t)MTOT * THREE_D];   // [B*T, 3D]
__device__ float g_attn[(size_t)MTOT * DD];       // [B*T, D]

// ---------------------------------------------------------------------------
// SGEMM: C[M,N] = A[M,K] @ B[N,K]^T (+bias[n]).  BM=BN=128, BK=16, 256 thr,
// 8x8 microtile.  M,N multiples of 128; K multiple of 16 (true for both uses).
// ---------------------------------------------------------------------------
template <bool BIAS>
__global__ __launch_bounds__(256)
void sgemm_bt(const float* __restrict__ A, const float* __restrict__ B,
              float* __restrict__ C, const float* __restrict__ bias,
              int M, int N, int K) {
    __shared__ float As[16][128];
    __shared__ float Bs[16][128];

    const int tid = threadIdx.x;
    const int tx  = tid & 15;
    const int ty  = tid >> 4;
    const int m0  = blockIdx.y * 128;
    const int n0  = blockIdx.x * 128;

    float acc[8][8];
#pragma unroll
    for (int i = 0; i < 8; i++)
#pragma unroll
        for (int j = 0; j < 8; j++) acc[i][j] = 0.f;

    for (int k0 = 0; k0 < K; k0 += 16) {
#pragma unroll
        for (int it = 0; it < 2; it++) {
            int f   = tid + it * 256;     // 0..511 float4 index
            int row = f >> 2;             // 0..127
            int c4  = (f & 3) * 4;        // 0,4,8,12
            float4 va = *(const float4*)&A[(long)(m0 + row) * K + k0 + c4];
            As[c4 + 0][row] = va.x; As[c4 + 1][row] = va.y;
            As[c4 + 2][row] = va.z; As[c4 + 3][row] = va.w;
            float4 vb = *(const float4*)&B[(long)(n0 + row) * K + k0 + c4];
            Bs[c4 + 0][row] = vb.x; Bs[c4 + 1][row] = vb.y;
            Bs[c4 + 2][row] = vb.z; Bs[c4 + 3][row] = vb.w;
        }
        __syncthreads();

#pragma unroll
        for (int k = 0; k < 16; k++) {
            float ra[8], rb[8];
#pragma unroll
            for (int i = 0; i < 8; i++) ra[i] = As[k][ty * 8 + i];
#pragma unroll
            for (int j = 0; j < 8; j++) rb[j] = Bs[k][tx * 8 + j];
#pragma unroll
            for (int i = 0; i < 8; i++)
#pragma unroll
                for (int j = 0; j < 8; j++) acc[i][j] += ra[i] * rb[j];
        }
        __syncthreads();
    }

#pragma unroll
    for (int i = 0; i < 8; i++) {
        int m = m0 + ty * 8 + i;
#pragma unroll
        for (int j = 0; j < 8; j += 4) {
            int n = n0 + tx * 8 + j;
            float4 v;
            v.x = acc[i][j];     v.y = acc[i][j + 1];
            v.z = acc[i][j + 2]; v.w = acc[i][j + 3];
            if (BIAS) {
                v.x += bias[n];     v.y += bias[n + 1];
                v.z += bias[n + 2]; v.w += bias[n + 3];
            }
            *(float4*)&C[(long)m * N + n] = v;
        }
    }
}

// ---------------------------------------------------------------------------
// Causal flash attention, fp32.  BM=BN=64, DH=64, 256 threads.
// Thread (ty,tx) owns S/P microtile rows [ty*4..+3] x cols [tx*4..+3] and
// O microtile rows [ty*4..+3] x dims [tx*4..+3].
// Smem: Qs,Ks transposed [d][r|j] stride 65; Vs [j][d] stride 65; Ps [j][r].
// ---------------------------------------------------------------------------
#define FPAD 65
#define FLASH_SMEM (4 * 64 * FPAD * sizeof(float))

__global__ __launch_bounds__(256)
void flash_kernel(const float* __restrict__ qkv, float* __restrict__ attn_out) {
    extern __shared__ float sm[];
    float* Qs = sm;                    // [d][r]
    float* Ks = Qs + 64 * FPAD;        // [d][j]
    float* Vs = Ks + 64 * FPAD;        // [j][d]
    float* Ps = Vs + 64 * FPAD;        // [j][r]

    const int tid = threadIdx.x;
    const int tx  = tid & 15;
    const int ty  = tid >> 4;
    const int qt  = blockIdx.x;        // q tile (64 rows)
    const int bh  = blockIdx.y;
    const int b   = bh / HH;
    const int h   = bh % HH;
    const int q0  = qt * 64;
    const int r0  = ty * 4;
    const int c0  = tx * 4;
    const float scale = 0.125f;        // DH^-0.5

    // Load Q tile (pre-scaled) transposed
#pragma unroll
    for (int i = 0; i < 16; i++) {
        int idx = tid + i * 256;       // 0..4095
        int r = idx >> 6, d = idx & 63;
        Qs[d * FPAD + r] =
            qkv[(long)(b * TT + q0 + r) * THREE_D + h * DHH + d] * scale;
    }

    float m_i[4], l_i[4], o[4][4];
#pragma unroll
    for (int i = 0; i < 4; i++) {
        m_i[i] = -CUDART_INF_F; l_i[i] = 0.f;
#pragma unroll
        for (int j = 0; j < 4; j++) o[i][j] = 0.f;
    }
    __syncthreads();

    for (int kt = 0; kt <= qt; kt++) {
        const int k0 = kt * 64;
        // Load K (transposed) and V tiles
#pragma unroll
        for (int i = 0; i < 16; i++) {
            int idx = tid + i * 256;
            int j = idx >> 6, d = idx & 63;
            long row = (long)(b * TT + k0 + j) * THREE_D + h * DHH + d;
            Ks[d * FPAD + j] = qkv[row + DD];        // K block
            Vs[j * FPAD + d] = qkv[row + 2 * DD];    // V block
        }
        __syncthreads();

        // S = Q K^T (already scaled via Q)
        float s[4][4];
#pragma unroll
        for (int i = 0; i < 4; i++)
#pragma unroll
            for (int j = 0; j < 4; j++) s[i][j] = 0.f;

#pragma unroll 8
        for (int d = 0; d < 64; d++) {
            float qv[4], kv[4];
#pragma unroll
            for (int i = 0; i < 4; i++) qv[i] = Qs[d * FPAD + r0 + i];
#pragma unroll
            for (int j = 0; j < 4; j++) kv[j] = Ks[d * FPAD + c0 + j];
#pragma unroll
            for (int i = 0; i < 4; i++)
#pragma unroll
                for (int j = 0; j < 4; j++) s[i][j] += qv[i] * kv[j];
        }

        if (kt == qt) {  // diagonal tile: causal mask
#pragma unroll
            for (int i = 0; i < 4; i++)
#pragma unroll
                for (int j = 0; j < 4; j++)
                    if (k0 + c0 + j > q0 + r0 + i) s[i][j] = -CUDART_INF_F;
        }

        // Online softmax per row (reduce across 16 tx lanes via shfl)
#pragma unroll
        for (int i = 0; i < 4; i++) {
            float mx = fmaxf(fmaxf(s[i][0], s[i][1]), fmaxf(s[i][2], s[i][3]));
            mx = fmaxf(mx, __shfl_xor_sync(0xffffffffu, mx, 8));
            mx = fmaxf(mx, __shfl_xor_sync(0xffffffffu, mx, 4));
            mx = fmaxf(mx, __shfl_xor_sync(0xffffffffu, mx, 2));
            mx = fmaxf(mx, __shfl_xor_sync(0xffffffffu, mx, 1));
            float m_new = fmaxf(m_i[i], mx);
            float alpha = __expf(m_i[i] - m_new);
            float rs = 0.f;
#pragma unroll
            for (int j = 0; j < 4; j++) {
                float p = __expf(s[i][j] - m_new);
                s[i][j] = p;
                rs += p;
            }
            rs += __shfl_xor_sync(0xffffffffu, rs, 8);
            rs += __shfl_xor_sync(0xffffffffu, rs, 4);
            rs += __shfl_xor_sync(0xffffffffu, rs, 2);
            rs += __shfl_xor_sync(0xffffffffu, rs, 1);
            l_i[i] = l_i[i] * alpha + rs;
            m_i[i] = m_new;
#pragma unroll
            for (int j = 0; j < 4; j++) o[i][j] *= alpha;
        }

        // Stage P transposed [j][r]
#pragma unroll
        for (int i = 0; i < 4; i++)
#pragma unroll
            for (int j = 0; j < 4; j++)
                Ps[(c0 + j) * FPAD + r0 + i] = s[i][j];
        __syncthreads();

        // O += P V  (thread dims = c0..c0+3)
#pragma unroll 8
        for (int j = 0; j < 64; j++) {
            float pv[4], vv[4];
#pragma unroll
            for (int i = 0; i < 4; i++) pv[i] = Ps[j * FPAD + r0 + i];
#pragma unroll
            for (int dd = 0; dd < 4; dd++) vv[dd] = Vs[j * FPAD + c0 + dd];
#pragma unroll
            for (int i = 0; i < 4; i++)
#pragma unroll
                for (int dd = 0; dd < 4; dd++) o[i][dd] += pv[i] * vv[dd];
        }
        __syncthreads();  // before next tile overwrites Ks/Vs/Ps
    }

    // Normalize + write
#pragma unroll
    for (int i = 0; i < 4; i++) {
        float inv = 1.0f / l_i[i];
#pragma unroll
        for (int dd = 0; dd < 4; dd++)
            attn_out[(long)(b * TT + q0 + r0 + i) * DD + h * DHH + c0 + dd] =
                o[i][dd] * inv;
    }
}

// ---------------------------------------------------------------------------
extern "C" void kernel_launch(void* const* d_in, const int* in_sizes, int n_in,
                              void* d_out, int out_size) {
    const float* x     = (const float*)d_in[0];
    const float* Wqkv  = (const float*)d_in[1];
    const float* Wproj = (const float*)d_in[2];
    const float* bproj = (const float*)d_in[3];
    float* out = (float*)d_out;

    float* qkv;
    float* attn;
    cudaGetSymbolAddress((void**)&qkv, g_qkv);
    cudaGetSymbolAddress((void**)&attn, g_attn);

    // 1) QKV = x @ Wqkv^T : [8192, 2304]
    {
        dim3 grid(THREE_D / 128, MTOT / 128);
        sgemm_bt<false><<<grid, 256>>>(x, Wqkv, qkv, nullptr,
                                       MTOT, THREE_D, DD);
    }

    // 2) causal flash attention -> g_attn [8192, 768]
    {
        cudaFuncSetAttribute(flash_kernel,
                             cudaFuncAttributeMaxDynamicSharedMemorySize,
                             (int)FLASH_SMEM);
        dim3 grid(TT / 64, BB * HH);
        flash_kernel<<<grid, 256, FLASH_SMEM>>>(qkv, attn);
    }

    // 3) out = attn @ Wproj^T + bproj : [8192, 768]
    {
        dim3 grid(DD / 128, MTOT / 128);
        sgemm_bt<true><<<grid, 256>>>(attn, Wproj, out, bproj,
                                      MTOT, DD, DD);
    }
}

// round 3
// speedup vs baseline: 1.4293x; 1.4293x over previous
#include <cuda_runtime.h>
#include <cuda_bf16.h>
#include <math_constants.h>
#include <cstdint>

// Problem constants
#define BB 4
#define TT 2048
#define DD 768
#define HH 12
#define DHH 64
#define THREE_D 2304
#define MTOT (BB*TT)       // 8192

// ---------------------------------------------------------------------------
// Scratch (device globals — no allocation allowed)
// ---------------------------------------------------------------------------
__device__ float g_qkv[(size_t)MTOT * THREE_D];        // [B*T, 3D] fp32
__device__ float g_attn[(size_t)MTOT * DD];            // [B*T, D]  fp32
__device__ __nv_bfloat16 g_xhi[(size_t)MTOT * DD];
__device__ __nv_bfloat16 g_xlo[(size_t)MTOT * DD];
__device__ __nv_bfloat16 g_whi[(size_t)THREE_D * DD];
__device__ __nv_bfloat16 g_wlo[(size_t)THREE_D * DD];
__device__ __nv_bfloat16 g_phi[(size_t)DD * DD];
__device__ __nv_bfloat16 g_plo[(size_t)DD * DD];
__device__ __nv_bfloat16 g_ahi[(size_t)MTOT * DD];
__device__ __nv_bfloat16 g_alo[(size_t)MTOT * DD];

// ---------------------------------------------------------------------------
// PTX helpers (generic sm_80+ ops only — tcgen05 is not available because the
// harness PTX stage targets sm_103 without the 'a' feature suffix)
// ---------------------------------------------------------------------------
__device__ __forceinline__ uint32_t smem_u32(const void* p) {
    uint32_t a;
    asm("{ .reg .u64 t; cvta.to.shared.u64 t, %1; cvt.u32.u64 %0, t; }"
        : "=r"(a) : "l"(p));
    return a;
}
__device__ __forceinline__ void cp_async16(uint32_t dst, const void* src) {
    asm volatile("cp.async.cg.shared.global [%0], [%1], 16;"
                 :: "r"(dst), "l"(src));
}
__device__ __forceinline__ void cp_commit() {
    asm volatile("cp.async.commit_group;" ::: "memory");
}
template <int N>
__device__ __forceinline__ void cp_wait() {
    asm volatile("cp.async.wait_group %0;" :: "n"(N) : "memory");
}
__device__ __forceinline__ void ldsm4(uint32_t& r0, uint32_t& r1,
                                      uint32_t& r2, uint32_t& r3, uint32_t a) {
    asm volatile("ldmatrix.sync.aligned.m8n8.x4.shared.b16 {%0,%1,%2,%3}, [%4];"
                 : "=r"(r0), "=r"(r1), "=r"(r2), "=r"(r3) : "r"(a));
}
__device__ __forceinline__ void mma_bf16(float* d, const uint32_t* a,
                                         const uint32_t* b) {
    asm volatile(
        "mma.sync.aligned.m16n8k16.row.col.f32.bf16.bf16.f32 "
        "{%0,%1,%2,%3}, {%4,%5,%6,%7}, {%8,%9}, {%0,%1,%2,%3};"
        : "+f"(d[0]), "+f"(d[1]), "+f"(d[2]), "+f"(d[3])
        : "r"(a[0]), "r"(a[1]), "r"(a[2]), "r"(a[3]), "r"(b[0]), "r"(b[1]));
}

// ---------------------------------------------------------------------------
// Split fp32 -> bf16 hi/lo
// ---------------------------------------------------------------------------
__global__ __launch_bounds__(256)
void split_kernel(const float* __restrict__ in, __nv_bfloat16* __restrict__ hi,
                  __nv_bfloat16* __restrict__ lo, int n4) {
    int i = blockIdx.x * blockDim.x + threadIdx.x;
    if (i >= n4) return;
    float4 v = ((const float4*)in)[i];
    float vv[4] = {v.x, v.y, v.z, v.w};
    __nv_bfloat16 h[4], l[4];
#pragma unroll
    for (int j = 0; j < 4; j++) {
        h[j] = __float2bfloat16(vv[j]);
        l[j] = __float2bfloat16(vv[j] - __bfloat162float(h[j]));
    }
    __nv_bfloat162 h01; h01.x = h[0]; h01.y = h[1];
    __nv_bfloat162 h23; h23.x = h[2]; h23.y = h[3];
    __nv_bfloat162 l01; l01.x = l[0]; l01.y = l[1];
    __nv_bfloat162 l23; l23.x = l[2]; l23.y = l[3];
    ((__nv_bfloat162*)hi)[i * 2 + 0] = h01;
    ((__nv_bfloat162*)hi)[i * 2 + 1] = h23;
    ((__nv_bfloat162*)lo)[i * 2 + 0] = l01;
    ((__nv_bfloat162*)lo)[i * 2 + 1] = l23;
}

// ---------------------------------------------------------------------------
// mma.sync GEMM: C[M,N] = A[M,K] @ B[N,K]^T (+bias), hi/lo bf16 inputs.
// CTA tile 128x128, 8 warps @ 32x64, BK=32, cp.async double-buffered smem.
// smem tiles: [buf][4 tiles: Ahi,Alo,Bhi,Blo][128 rows][40 bf16 (pad)]
// ---------------------------------------------------------------------------
#define TSTRIDE   40                      // bf16 elems per smem row (80 B)
#define TILE_B    (128 * TSTRIDE * 2)     // 10240 B per tile
#define BUF_B     (4 * TILE_B)            // 40960 B per stage buffer
#define GEMM_SMEM (2 * BUF_B)             // 81920 B

template <bool BIAS>
__global__ __launch_bounds__(256)
void gemm_mma(const __nv_bfloat16* __restrict__ Ahi, const __nv_bfloat16* __restrict__ Alo,
              const __nv_bfloat16* __restrict__ Bhi, const __nv_bfloat16* __restrict__ Blo,
              float* __restrict__ C, const float* __restrict__ bias,
              int M, int N, int K) {
    extern __shared__ char smem[];
    const uint32_t sb = smem_u32(smem);
    const int tid = threadIdx.x;
    const int lane = tid & 31;
    const int warp = tid >> 5;
    const int wm = warp & 3;       // 0..3  -> rows wm*32
    const int wn = warp >> 2;      // 0..1  -> cols wn*64
    const int m0 = blockIdx.y * 128;
    const int n0 = blockIdx.x * 128;

    float acc[2][8][4];
#pragma unroll
    for (int f = 0; f < 2; f++)
#pragma unroll
        for (int j = 0; j < 8; j++)
#pragma unroll
            for (int e = 0; e < 4; e++) acc[f][j][e] = 0.f;

    const int nstage = K / 32;

    // stage issue: 4 tiles x 128 rows x 32 bf16, 16B chunks
#define ISSUE(s)                                                               \
    do {                                                                       \
        const int k0_ = (s) * 32;                                              \
        const uint32_t db_ = sb + ((s) & 1) * BUF_B;                           \
        _Pragma("unroll")                                                      \
        for (int tile = 0; tile < 4; tile++) {                                 \
            const __nv_bfloat16* src =                                         \
                (tile == 0) ? Ahi : (tile == 1) ? Alo : (tile == 2) ? Bhi : Blo; \
            const int base = (tile < 2) ? m0 : n0;                             \
            _Pragma("unroll")                                                  \
            for (int i = 0; i < 2; i++) {                                      \
                int c = tid + i * 256;           /* 0..511 */                  \
                int row = c >> 2, g = c & 3;                                   \
                cp_async16(db_ + tile * TILE_B + row * 80 + g * 16,            \
                           src + (size_t)(base + row) * K + k0_ + g * 8);      \
            }                                                                  \
        }                                                                      \
        cp_commit();                                                           \
    } while (0)

    ISSUE(0);

    for (int s = 0; s < nstage; s++) {
        if (s + 1 < nstage) { ISSUE(s + 1); cp_wait<1>(); }
        else                { cp_wait<0>(); }
        __syncthreads();

        const uint32_t bufb = sb + (s & 1) * BUF_B;
        const int q = lane >> 3;
#pragma unroll
        for (int kk = 0; kk < 32; kk += 16) {
            uint32_t Ah[2][4], Al[2][4], Bh[8][2], Bl[8][2];
#pragma unroll
            for (int f = 0; f < 2; f++) {
                uint32_t arow = wm * 32 + f * 16 + (lane & 15);
                uint32_t aoff = arow * 80 + (kk + (lane >> 4) * 8) * 2;
                ldsm4(Ah[f][0], Ah[f][1], Ah[f][2], Ah[f][3], bufb + aoff);
                ldsm4(Al[f][0], Al[f][1], Al[f][2], Al[f][3],
                      bufb + TILE_B + aoff);
            }
#pragma unroll
            for (int p = 0; p < 4; p++) {
                uint32_t brow = wn * 64 + p * 16 + (q >> 1) * 8 + (lane & 7);
                uint32_t boff = brow * 80 + (kk + (q & 1) * 8) * 2;
                ldsm4(Bh[2 * p][0], Bh[2 * p][1], Bh[2 * p + 1][0],
                      Bh[2 * p + 1][1], bufb + 2 * TILE_B + boff);
                ldsm4(Bl[2 * p][0], Bl[2 * p][1], Bl[2 * p + 1][0],
                      Bl[2 * p + 1][1], bufb + 3 * TILE_B + boff);
            }
#pragma unroll
            for (int f = 0; f < 2; f++)
#pragma unroll
                for (int j = 0; j < 8; j++) {
                    mma_bf16(acc[f][j], Ah[f], Bh[j]);
                    mma_bf16(acc[f][j], Ah[f], Bl[j]);
                    mma_bf16(acc[f][j], Al[f], Bh[j]);
                }
        }
        __syncthreads();
    }

    // epilogue
#pragma unroll
    for (int f = 0; f < 2; f++) {
        const int mrow = m0 + wm * 32 + f * 16 + (lane >> 2);
#pragma unroll
        for (int j = 0; j < 8; j++) {
            const int n = n0 + wn * 64 + j * 8 + (lane & 3) * 2;
            float2 v0, v1;
            v0.x = acc[f][j][0]; v0.y = acc[f][j][1];
            v1.x = acc[f][j][2]; v1.y = acc[f][j][3];
            if (BIAS) {
                float b0 = bias[n], b1 = bias[n + 1];
                v0.x += b0; v0.y += b1; v1.x += b0; v1.y += b1;
            }
            *(float2*)&C[(size_t)mrow * N + n] = v0;
            *(float2*)&C[(size_t)(mrow + 8) * N + n] = v1;
        }
    }
}

// ---------------------------------------------------------------------------
// Causal flash attention, fp32 (unchanged — passing)
// ---------------------------------------------------------------------------
#define FPAD 65
#define FLASH_SMEM (4 * 64 * FPAD * sizeof(float))

__global__ __launch_bounds__(256)
void flash_kernel(const float* __restrict__ qkv, float* __restrict__ attn_out) {
    extern __shared__ float sm[];
    float* Qs = sm;
    float* Ks = Qs + 64 * FPAD;
    float* Vs = Ks + 64 * FPAD;
    float* Ps = Vs + 64 * FPAD;

    const int tid = threadIdx.x;
    const int tx  = tid & 15;
    const int ty  = tid >> 4;
    const int qt  = blockIdx.x;
    const int bh  = blockIdx.y;
    const int b   = bh / HH;
    const int h   = bh % HH;
    const int q0  = qt * 64;
    const int r0  = ty * 4;
    const int c0  = tx * 4;
    const float scale = 0.125f;

#pragma unroll
    for (int i = 0; i < 16; i++) {
        int idx = tid + i * 256;
        int r = idx >> 6, d = idx & 63;
        Qs[d * FPAD + r] =
            qkv[(long)(b * TT + q0 + r) * THREE_D + h * DHH + d] * scale;
    }

    float m_i[4], l_i[4], o[4][4];
#pragma unroll
    for (int i = 0; i < 4; i++) {
        m_i[i] = -CUDART_INF_F; l_i[i] = 0.f;
#pragma unroll
        for (int j = 0; j < 4; j++) o[i][j] = 0.f;
    }
    __syncthreads();

    for (int kt = 0; kt <= qt; kt++) {
        const int k0 = kt * 64;
#pragma unroll
        for (int i = 0; i < 16; i++) {
            int idx = tid + i * 256;
            int j = idx >> 6, d = idx & 63;
            long row = (long)(b * TT + k0 + j) * THREE_D + h * DHH + d;
            Ks[d * FPAD + j] = qkv[row + DD];
            Vs[j * FPAD + d] = qkv[row + 2 * DD];
        }
        __syncthreads();

        float s[4][4];
#pragma unroll
        for (int i = 0; i < 4; i++)
#pragma unroll
            for (int j = 0; j < 4; j++) s[i][j] = 0.f;

#pragma unroll 8
        for (int d = 0; d < 64; d++) {
            float qv[4], kv[4];
#pragma unroll
            for (int i = 0; i < 4; i++) qv[i] = Qs[d * FPAD + r0 + i];
#pragma unroll
            for (int j = 0; j < 4; j++) kv[j] = Ks[d * FPAD + c0 + j];
#pragma unroll
            for (int i = 0; i < 4; i++)
#pragma unroll
                for (int j = 0; j < 4; j++) s[i][j] += qv[i] * kv[j];
        }

        if (kt == qt) {
#pragma unroll
            for (int i = 0; i < 4; i++)
#pragma unroll
                for (int j = 0; j < 4; j++)
                    if (k0 + c0 + j > q0 + r0 + i) s[i][j] = -CUDART_INF_F;
        }

#pragma unroll
        for (int i = 0; i < 4; i++) {
            float mx = fmaxf(fmaxf(s[i][0], s[i][1]), fmaxf(s[i][2], s[i][3]));
            mx = fmaxf(mx, __shfl_xor_sync(0xffffffffu, mx, 8));
            mx = fmaxf(mx, __shfl_xor_sync(0xffffffffu, mx, 4));
            mx = fmaxf(mx, __shfl_xor_sync(0xffffffffu, mx, 2));
            mx = fmaxf(mx, __shfl_xor_sync(0xffffffffu, mx, 1));
            float m_new = fmaxf(m_i[i], mx);
            float alpha = __expf(m_i[i] - m_new);
            float rs = 0.f;
#pragma unroll
            for (int j = 0; j < 4; j++) {
                float p = __expf(s[i][j] - m_new);
                s[i][j] = p;
                rs += p;
            }
            rs += __shfl_xor_sync(0xffffffffu, rs, 8);
            rs += __shfl_xor_sync(0xffffffffu, rs, 4);
            rs += __shfl_xor_sync(0xffffffffu, rs, 2);
            rs += __shfl_xor_sync(0xffffffffu, rs, 1);
            l_i[i] = l_i[i] * alpha + rs;
            m_i[i] = m_new;
#pragma unroll
            for (int j = 0; j < 4; j++) o[i][j] *= alpha;
        }

#pragma unroll
        for (int i = 0; i < 4; i++)
#pragma unroll
            for (int j = 0; j < 4; j++)
                Ps[(c0 + j) * FPAD + r0 + i] = s[i][j];
        __syncthreads();

#pragma unroll 8
        for (int j = 0; j < 64; j++) {
            float pv[4], vv[4];
#pragma unroll
            for (int i = 0; i < 4; i++) pv[i] = Ps[j * FPAD + r0 + i];
#pragma unroll
            for (int dd = 0; dd < 4; dd++) vv[dd] = Vs[j * FPAD + c0 + dd];
#pragma unroll
            for (int i = 0; i < 4; i++)
#pragma unroll
                for (int dd = 0; dd < 4; dd++) o[i][dd] += pv[i] * vv[dd];
        }
        __syncthreads();
    }

#pragma unroll
    for (int i = 0; i < 4; i++) {
        float inv = 1.0f / l_i[i];
#pragma unroll
        for (int dd = 0; dd < 4; dd++)
            attn_out[(long)(b * TT + q0 + r0 + i) * DD + h * DHH + c0 + dd] =
                o[i][dd] * inv;
    }
}

// ---------------------------------------------------------------------------
extern "C" void kernel_launch(void* const* d_in, const int* in_sizes, int n_in,
                              void* d_out, int out_size) {
    const float* x     = (const float*)d_in[0];
    const float* Wqkv  = (const float*)d_in[1];
    const float* Wproj = (const float*)d_in[2];
    const float* bproj = (const float*)d_in[3];
    float* out = (float*)d_out;

    float *qkv, *attn;
    __nv_bfloat16 *xhi, *xlo, *whi, *wlo, *phi, *plo, *ahi, *alo;
    cudaGetSymbolAddress((void**)&qkv, g_qkv);
    cudaGetSymbolAddress((void**)&attn, g_attn);
    cudaGetSymbolAddress((void**)&xhi, g_xhi);
    cudaGetSymbolAddress((void**)&xlo, g_xlo);
    cudaGetSymbolAddress((void**)&whi, g_whi);
    cudaGetSymbolAddress((void**)&wlo, g_wlo);
    cudaGetSymbolAddress((void**)&phi, g_phi);
    cudaGetSymbolAddress((void**)&plo, g_plo);
    cudaGetSymbolAddress((void**)&ahi, g_ahi);
    cudaGetSymbolAddress((void**)&alo, g_alo);

    cudaFuncSetAttribute(gemm_mma<false>,
                         cudaFuncAttributeMaxDynamicSharedMemorySize, GEMM_SMEM);
    cudaFuncSetAttribute(gemm_mma<true>,
                         cudaFuncAttributeMaxDynamicSharedMemorySize, GEMM_SMEM);
    cudaFuncSetAttribute(flash_kernel,
                         cudaFuncAttributeMaxDynamicSharedMemorySize, (int)FLASH_SMEM);

    // Split inputs to bf16 hi/lo
    {
        int n4 = MTOT * DD / 4;
        split_kernel<<<(n4 + 255) / 256, 256>>>(x, xhi, xlo, n4);
        n4 = THREE_D * DD / 4;
        split_kernel<<<(n4 + 255) / 256, 256>>>(Wqkv, whi, wlo, n4);
        n4 = DD * DD / 4;
        split_kernel<<<(n4 + 255) / 256, 256>>>(Wproj, phi, plo, n4);
    }

    // 1) QKV = x @ Wqkv^T : [8192, 2304]
    {
        dim3 grid(THREE_D / 128, MTOT / 128);
        gemm_mma<false><<<grid, 256, GEMM_SMEM>>>(xhi, xlo, whi, wlo, qkv,
                                                  nullptr, MTOT, THREE_D, DD);
    }

    // 2) causal flash attention -> g_attn [8192, 768]
    {
        dim3 grid(TT / 64, BB * HH);
        flash_kernel<<<grid, 256, FLASH_SMEM>>>(qkv, attn);
    }

    // 3) split attn, then out = attn @ Wproj^T + bproj
    {
        int n4 = MTOT * DD / 4;
        split_kernel<<<(n4 + 255) / 256, 256>>>(attn, ahi, alo, n4);
        dim3 grid(DD / 128, MTOT / 128);
        gemm_mma<true><<<grid, 256, GEMM_SMEM>>>(ahi, alo, phi, plo, out,
                                                 bproj, MTOT, DD, DD);
    }
}

// round 5
// speedup vs baseline: 1.8643x; 1.3043x over previous
#include <cuda_runtime.h>
#include <cuda_bf16.h>
#include <math_constants.h>
#include <cstdint>

// Problem constants
#define BB 4
#define TT 2048
#define DD 768
#define HH 12
#define DHH 64
#define THREE_D 2304
#define MTOT (BB*TT)       // 8192
#define QSCALE 0.18033688011112042f   // 0.125 * log2(e)

// ---------------------------------------------------------------------------
// Scratch (device globals — no allocation allowed)
// ---------------------------------------------------------------------------
#define QKV_ELEMS ((size_t)BB * HH * TT * DHH)   // 6291456 per array
__device__ __nv_bfloat16 g_xhi[(size_t)MTOT * DD];
__device__ __nv_bfloat16 g_xlo[(size_t)MTOT * DD];
__device__ __nv_bfloat16 g_whi[(size_t)THREE_D * DD];
__device__ __nv_bfloat16 g_wlo[(size_t)THREE_D * DD];
__device__ __nv_bfloat16 g_phi[(size_t)DD * DD];
__device__ __nv_bfloat16 g_plo[(size_t)DD * DD];
__device__ __nv_bfloat16 g_ahi[(size_t)MTOT * DD];
__device__ __nv_bfloat16 g_alo[(size_t)MTOT * DD];
__device__ __nv_bfloat16 g_qh[QKV_ELEMS];
__device__ __nv_bfloat16 g_ql[QKV_ELEMS];
__device__ __nv_bfloat16 g_kh[QKV_ELEMS];
__device__ __nv_bfloat16 g_kl[QKV_ELEMS];
__device__ __nv_bfloat16 g_vh[QKV_ELEMS];
__device__ __nv_bfloat16 g_vl[QKV_ELEMS];

// ---------------------------------------------------------------------------
// PTX helpers (generic sm_80+ only — tcgen05 rejected: harness targets sm_103)
// ---------------------------------------------------------------------------
__device__ __forceinline__ uint32_t smem_u32(const void* p) {
    uint32_t a;
    asm("{ .reg .u64 t; cvta.to.shared.u64 t, %1; cvt.u32.u64 %0, t; }"
        : "=r"(a) : "l"(p));
    return a;
}
__device__ __forceinline__ void cp_async16(uint32_t dst, const void* src) {
    asm volatile("cp.async.cg.shared.global [%0], [%1], 16;"
                 :: "r"(dst), "l"(src));
}
__device__ __forceinline__ void cp_commit() {
    asm volatile("cp.async.commit_group;" ::: "memory");
}
template <int N>
__device__ __forceinline__ void cp_wait() {
    asm volatile("cp.async.wait_group %0;" :: "n"(N) : "memory");
}
__device__ __forceinline__ void ldsm4(uint32_t& r0, uint32_t& r1,
                                      uint32_t& r2, uint32_t& r3, uint32_t a) {
    asm volatile("ldmatrix.sync.aligned.m8n8.x4.shared.b16 {%0,%1,%2,%3}, [%4];"
                 : "=r"(r0), "=r"(r1), "=r"(r2), "=r"(r3) : "r"(a));
}
__device__ __forceinline__ void ldsm4t(uint32_t& r0, uint32_t& r1,
                                       uint32_t& r2, uint32_t& r3, uint32_t a) {
    asm volatile("ldmatrix.sync.aligned.m8n8.x4.trans.shared.b16 {%0,%1,%2,%3}, [%4];"
                 : "=r"(r0), "=r"(r1), "=r"(r2), "=r"(r3) : "r"(a));
}
__device__ __forceinline__ void mma_bf16(float* d, const uint32_t* a,
                                         const uint32_t* b) {
    asm volatile(
        "mma.sync.aligned.m16n8k16.row.col.f32.bf16.bf16.f32 "
        "{%0,%1,%2,%3}, {%4,%5,%6,%7}, {%8,%9}, {%0,%1,%2,%3};"
        : "+f"(d[0]), "+f"(d[1]), "+f"(d[2]), "+f"(d[3])
        : "r"(a[0]), "r"(a[1]), "r"(a[2]), "r"(a[3]), "r"(b[0]), "r"(b[1]));
}
__device__ __forceinline__ uint32_t pack_bf16x2(float lo, float hi) {
    uint32_t r;
    asm("cvt.rn.bf16x2.f32 %0, %1, %2;" : "=r"(r) : "f"(hi), "f"(lo));
    return r;
}
__device__ __forceinline__ float ex2(float x) {
    float y;
    asm("ex2.approx.ftz.f32 %0, %1;" : "=f"(y) : "f"(x));
    return y;
}
// trunc-split: hi = top-16-bits of two floats packed; residual exact
__device__ __forceinline__ void split_store(float v0, float v1,
                                            __nv_bfloat16* hi, __nv_bfloat16* lo) {
    uint32_t u0 = __float_as_uint(v0), u1 = __float_as_uint(v1);
    *(uint32_t*)hi = __byte_perm(u0, u1, 0x7632);
    float r0 = v0 - __uint_as_float(u0 & 0xffff0000u);
    float r1 = v1 - __uint_as_float(u1 & 0xffff0000u);
    *(uint32_t*)lo = pack_bf16x2(r0, r1);
}

// ---------------------------------------------------------------------------
// Split fp32 -> bf16 hi/lo (precompute for x, Wqkv, Wproj)
// ---------------------------------------------------------------------------
__global__ __launch_bounds__(256)
void split_kernel(const float* __restrict__ in, __nv_bfloat16* __restrict__ hi,
                  __nv_bfloat16* __restrict__ lo, int n4) {
    int i = blockIdx.x * blockDim.x + threadIdx.x;
    if (i >= n4) return;
    float4 v = ((const float4*)in)[i];
    float vv[4] = {v.x, v.y, v.z, v.w};
#pragma unroll
    for (int j = 0; j < 4; j += 2)
        split_store(vv[j], vv[j + 1], hi + (size_t)i * 4 + j, lo + (size_t)i * 4 + j);
}

// ---------------------------------------------------------------------------
// mma.sync GEMM: C[M,N] = A[M,K] @ B[N,K]^T, hi/lo bf16 inputs, 3-MMA split.
// CTA 128x128, 8 warps @ 32x64, BK=32, cp.async double-buffered.
// MODE 0: fp32 out + bias.  MODE 1: QKV epilogue -> head-major bf16 hi/lo,
//         Q pre-scaled by QSCALE.
// ---------------------------------------------------------------------------
#define TILE_B    (128 * 40 * 2)          // 10240 B per tile (stride 40 bf16)
#define BUF_B     (4 * TILE_B)
#define GEMM_SMEM (2 * BUF_B)             // 81920 B

template <int MODE>
__global__ __launch_bounds__(256)
void gemm_mma(const __nv_bfloat16* __restrict__ Ahi, const __nv_bfloat16* __restrict__ Alo,
              const __nv_bfloat16* __restrict__ Bhi, const __nv_bfloat16* __restrict__ Blo,
              float* __restrict__ C, const float* __restrict__ bias,
              __nv_bfloat16* __restrict__ qh, __nv_bfloat16* __restrict__ ql,
              __nv_bfloat16* __restrict__ kh, __nv_bfloat16* __restrict__ kl,
              __nv_bfloat16* __restrict__ vh, __nv_bfloat16* __restrict__ vl,
              int M, int N, int K) {
    extern __shared__ char smem[];
    const uint32_t sb = smem_u32(smem);
    const int tid = threadIdx.x;
    const int lane = tid & 31;
    const int warp = tid >> 5;
    const int wm = warp & 3;
    const int wn = warp >> 2;
    const int m0 = blockIdx.y * 128;
    const int n0 = blockIdx.x * 128;

    float acc[2][8][4];
#pragma unroll
    for (int f = 0; f < 2; f++)
#pragma unroll
        for (int j = 0; j < 8; j++)
#pragma unroll
            for (int e = 0; e < 4; e++) acc[f][j][e] = 0.f;

    const int nstage = K / 32;

#define ISSUE(s)                                                               \
    do {                                                                       \
        const int k0_ = (s) * 32;                                              \
        const uint32_t db_ = sb + ((s) & 1) * BUF_B;                           \
        _Pragma("unroll")                                                      \
        for (int tile = 0; tile < 4; tile++) {                                 \
            const __nv_bfloat16* src =                                         \
                (tile == 0) ? Ahi : (tile == 1) ? Alo : (tile == 2) ? Bhi : Blo; \
            const int base = (tile < 2) ? m0 : n0;                             \
            _Pragma("unroll")                                                  \
            for (int i = 0; i < 2; i++) {                                      \
                int c = tid + i * 256;                                         \
                int row = c >> 2, g = c & 3;                                   \
                cp_async16(db_ + tile * TILE_B + row * 80 + g * 16,            \
                           src + (size_t)(base + row) * K + k0_ + g * 8);      \
            }                                                                  \
        }                                                                      \
        cp_commit();                                                           \
    } while (0)

    ISSUE(0);

    for (int s = 0; s < nstage; s++) {
        if (s + 1 < nstage) { ISSUE(s + 1); cp_wait<1>(); }
        else                { cp_wait<0>(); }
        __syncthreads();

        const uint32_t bufb = sb + (s & 1) * BUF_B;
        const int q = lane >> 3;
#pragma unroll
        for (int kk = 0; kk < 32; kk += 16) {
            uint32_t Ah[2][4], Al[2][4], Bh[8][2], Bl[8][2];
#pragma unroll
            for (int f = 0; f < 2; f++) {
                uint32_t arow = wm * 32 + f * 16 + (lane & 15);
                uint32_t aoff = arow * 80 + (kk + (lane >> 4) * 8) * 2;
                ldsm4(Ah[f][0], Ah[f][1], Ah[f][2], Ah[f][3], bufb + aoff);
                ldsm4(Al[f][0], Al[f][1], Al[f][2], Al[f][3],
                      bufb + TILE_B + aoff);
            }
#pragma unroll
            for (int p = 0; p < 4; p++) {
                uint32_t brow = wn * 64 + p * 16 + (q >> 1) * 8 + (lane & 7);
                uint32_t boff = brow * 80 + (kk + (q & 1) * 8) * 2;
                ldsm4(Bh[2 * p][0], Bh[2 * p][1], Bh[2 * p + 1][0],
                      Bh[2 * p + 1][1], bufb + 2 * TILE_B + boff);
                ldsm4(Bl[2 * p][0], Bl[2 * p][1], Bl[2 * p + 1][0],
                      Bl[2 * p + 1][1], bufb + 3 * TILE_B + boff);
            }
#pragma unroll
            for (int f = 0; f < 2; f++)
#pragma unroll
                for (int j = 0; j < 8; j++) {
                    mma_bf16(acc[f][j], Ah[f], Bh[j]);
                    mma_bf16(acc[f][j], Ah[f], Bl[j]);
                    mma_bf16(acc[f][j], Al[f], Bh[j]);
                }
        }
        __syncthreads();
    }

    // epilogue
#pragma unroll
    for (int f = 0; f < 2; f++) {
        const int mrow = m0 + wm * 32 + f * 16 + (lane >> 2);
#pragma unroll
        for (int j = 0; j < 8; j++) {
            const int n = n0 + wn * 64 + j * 8 + (lane & 3) * 2;
            if (MODE == 0) {
                float2 v0, v1;
                v0.x = acc[f][j][0]; v0.y = acc[f][j][1];
                v1.x = acc[f][j][2]; v1.y = acc[f][j][3];
                float b0 = bias[n], b1 = bias[n + 1];
                v0.x += b0; v0.y += b1; v1.x += b0; v1.y += b1;
                *(float2*)&C[(size_t)mrow * N + n] = v0;
                *(float2*)&C[(size_t)(mrow + 8) * N + n] = v1;
            } else {
                const int type = n / DD;           // 0=q, 1=k, 2=v
                const int h = (n - type * DD) >> 6;
                const int d = n & 63;
                const float sc = (type == 0) ? QSCALE : 1.0f;
                __nv_bfloat16* dh = (type == 0) ? qh : (type == 1) ? kh : vh;
                __nv_bfloat16* dl = (type == 0) ? ql : (type == 1) ? kl : vl;
                const int bI = mrow >> 11;
                const int t = mrow & 2047;
                size_t idx = ((size_t)(bI * HH + h) * TT + t) * DHH + d;
                split_store(acc[f][j][0] * sc, acc[f][j][1] * sc, dh + idx, dl + idx);
                idx += (size_t)8 * DHH;            // row + 8, same head
                split_store(acc[f][j][2] * sc, acc[f][j][3] * sc, dh + idx, dl + idx);
            }
        }
    }
}

// ---------------------------------------------------------------------------
// Causal flash attention, mma.sync bf16 hi/lo.
// BM=128 (8 warps x 16 rows), BN=64, DH=64.  K/V double-buffered cp.async.
// Q fragments in registers.  Softmax in log2 domain (Q pre-scaled by QSCALE).
// Writes attn output directly as bf16 hi/lo [MTOT][DD].
// ---------------------------------------------------------------------------
#define KV_TILE_B  (64 * 144)             // 64 rows x 144 B (72 bf16, padded)
#define KV_STAGE   (4 * KV_TILE_B)        // 36864
#define FLASH_SMEM (2 * KV_STAGE)         // 73728

__global__ __launch_bounds__(256)
void flash_mma(const __nv_bfloat16* __restrict__ qh_, const __nv_bfloat16* __restrict__ ql_,
               const __nv_bfloat16* __restrict__ kh_, const __nv_bfloat16* __restrict__ kl_,
               const __nv_bfloat16* __restrict__ vh_, const __nv_bfloat16* __restrict__ vl_,
               __nv_bfloat16* __restrict__ oh_, __nv_bfloat16* __restrict__ ol_) {
    extern __shared__ char smem[];
    const uint32_t sb = smem_u32(smem);
    const int tid = threadIdx.x;
    const int lane = tid & 31;
    const int w = tid >> 5;
    const int qt = gridDim.x - 1 - blockIdx.x;   // heavy tiles first
    const int bh = blockIdx.y;
    const int q0 = qt * 128;
    const int nkt = 2 * qt + 2;
    const size_t hbase = (size_t)bh * TT * DHH;

#define FISSUE(s_)                                                             \
    do {                                                                       \
        const int k0_ = (s_) * 64;                                             \
        const uint32_t db_ = sb + ((s_) & 1) * KV_STAGE;                       \
        _Pragma("unroll")                                                      \
        for (int i = 0; i < 8; i++) {                                          \
            int c = tid + i * 256;                                             \
            int arr = c >> 9, cc = c & 511, row = cc >> 3, g = cc & 7;         \
            const __nv_bfloat16* src =                                         \
                (arr == 0) ? kh_ : (arr == 1) ? kl_ : (arr == 2) ? vh_ : vl_;  \
            cp_async16(db_ + arr * KV_TILE_B + row * 144 + g * 16,             \
                       src + hbase + (size_t)(k0_ + row) * DHH + g * 8);       \
        }                                                                      \
        cp_commit();                                                           \
    } while (0)

    FISSUE(0);

    // Q fragments (A-frags for 4 k-steps, hi+lo) — register resident
    uint32_t Qh[4][4], Ql[4][4];
    {
        const size_t qoff = hbase + (size_t)(q0 + w * 16) * DHH;
        const int r = lane >> 2;
        const int c = (lane & 3) * 2;
#pragma unroll
        for (int kk = 0; kk < 4; kk++) {
            const int cb = c + kk * 16;
            Qh[kk][0] = *(const uint32_t*)(qh_ + qoff + r * 64 + cb);
            Qh[kk][1] = *(const uint32_t*)(qh_ + qoff + (r + 8) * 64 + cb);
            Qh[kk][2] = *(const uint32_t*)(qh_ + qoff + r * 64 + cb + 8);
            Qh[kk][3] = *(const uint32_t*)(qh_ + qoff + (r + 8) * 64 + cb + 8);
            Ql[kk][0] = *(const uint32_t*)(ql_ + qoff + r * 64 + cb);
            Ql[kk][1] = *(const uint32_t*)(ql_ + qoff + (r + 8) * 64 + cb);
            Ql[kk][2] = *(const uint32_t*)(ql_ + qoff + r * 64 + cb + 8);
            Ql[kk][3] = *(const uint32_t*)(ql_ + qoff + (r + 8) * 64 + cb + 8);
        }
    }

    float m_[2] = {-CUDART_INF_F, -CUDART_INF_F};
    float l_[2] = {0.f, 0.f};
    float o[8][4];
#pragma unroll
    for (int j = 0; j < 8; j++)
#pragma unroll
        for (int e = 0; e < 4; e++) o[j][e] = 0.f;

    for (int kt = 0; kt < nkt; kt++) {
        if (kt + 1 < nkt) { FISSUE(kt + 1); cp_wait<1>(); }
        else              { cp_wait<0>(); }
        __syncthreads();
        const uint32_t buf = sb + (kt & 1) * KV_STAGE;

        // ---- S = Q K^T ----
        float s[8][4];
#pragma unroll
        for (int j = 0; j < 8; j++)
#pragma unroll
            for (int e = 0; e < 4; e++) s[j][e] = 0.f;

        const int qg = lane >> 3;
#pragma unroll
        for (int kk = 0; kk < 4; kk++) {
#pragma unroll
            for (int p = 0; p < 4; p++) {
                const uint32_t boff =
                    (uint32_t)((p * 16 + (qg >> 1) * 8 + (lane & 7)) * 144 +
                               (kk * 16 + (qg & 1) * 8) * 2);
                uint32_t B0[2], B1[2], C0[2], C1[2];
                ldsm4(B0[0], B0[1], B1[0], B1[1], buf + boff);
                ldsm4(C0[0], C0[1], C1[0], C1[1], buf + KV_TILE_B + boff);
                mma_bf16(s[2 * p],     Qh[kk], B0);
                mma_bf16(s[2 * p],     Qh[kk], C0);
                mma_bf16(s[2 * p],     Ql[kk], B0);
                mma_bf16(s[2 * p + 1], Qh[kk], B1);
                mma_bf16(s[2 * p + 1], Qh[kk], C1);
                mma_bf16(s[2 * p + 1], Ql[kk], B1);
            }
        }

        // ---- causal mask (only near-diagonal tiles) ----
        const int k0 = kt * 64;
        if (k0 + 63 > q0 + w * 16) {
            const int qr0 = q0 + w * 16 + (lane >> 2);
#pragma unroll
            for (int j = 0; j < 8; j++) {
                const int cb = k0 + j * 8 + (lane & 3) * 2;
#pragma unroll
                for (int e = 0; e < 4; e++) {
                    const int col = cb + (e & 1);
                    const int qr = qr0 + ((e >> 1) << 3);
                    if (col > qr) s[j][e] = -CUDART_INF_F;
                }
            }
        }

        // ---- online softmax (log2 domain) ----
#pragma unroll
        for (int rg = 0; rg < 2; rg++) {
            float mx = s[0][rg * 2];
#pragma unroll
            for (int j = 0; j < 8; j++)
                mx = fmaxf(mx, fmaxf(s[j][rg * 2], s[j][rg * 2 + 1]));
            mx = fmaxf(mx, __shfl_xor_sync(0xffffffffu, mx, 1));
            mx = fmaxf(mx, __shfl_xor_sync(0xffffffffu, mx, 2));
            const float mn = fmaxf(m_[rg], mx);
            const float al = ex2(m_[rg] - mn);
            float sum = 0.f;
#pragma unroll
            for (int j = 0; j < 8; j++) {
                float p0 = ex2(s[j][rg * 2] - mn);
                float p1 = ex2(s[j][rg * 2 + 1] - mn);
                s[j][rg * 2] = p0; s[j][rg * 2 + 1] = p1;
                sum += p0 + p1;
            }
            sum += __shfl_xor_sync(0xffffffffu, sum, 1);
            sum += __shfl_xor_sync(0xffffffffu, sum, 2);
            l_[rg] = l_[rg] * al + sum;
            m_[rg] = mn;
#pragma unroll
            for (int j = 0; j < 8; j++) {
                o[j][rg * 2] *= al;
                o[j][rg * 2 + 1] *= al;
            }
        }

        // ---- O += P V ----
#pragma unroll
        for (int t = 0; t < 4; t++) {
            uint32_t Ph[4], Pl[4];
#pragma unroll
            for (int idx = 0; idx < 4; idx++) {
                const float v0 = s[2 * t + (idx >> 1)][(idx & 1) * 2 + 0];
                const float v1 = s[2 * t + (idx >> 1)][(idx & 1) * 2 + 1];
                const uint32_t u0 = __float_as_uint(v0);
                const uint32_t u1 = __float_as_uint(v1);
                Ph[idx] = __byte_perm(u0, u1, 0x7632);
                const float r0 = v0 - __uint_as_float(u0 & 0xffff0000u);
                const float r1 = v1 - __uint_as_float(u1 & 0xffff0000u);
                Pl[idx] = pack_bf16x2(r0, r1);
            }
            const int vrow = t * 16 + (lane & 7) + ((lane >> 3) & 1) * 8;
            const int vcb = (lane >> 4) * 8;
#pragma unroll
            for (int u = 0; u < 4; u++) {
                const uint32_t a =
                    buf + 2 * KV_TILE_B + vrow * 144 + (u * 16 + vcb) * 2;
                uint32_t V0[2], V1[2], W0[2], W1[2];
                ldsm4t(V0[0], V0[1], V1[0], V1[1], a);
                ldsm4t(W0[0], W0[1], W1[0], W1[1], a + KV_TILE_B);
                mma_bf16(o[2 * u],     Ph, V0);
                mma_bf16(o[2 * u],     Ph, W0);
                mma_bf16(o[2 * u],     Pl, V0);
                mma_bf16(o[2 * u + 1], Ph, V1);
                mma_bf16(o[2 * u + 1], Ph, W1);
                mma_bf16(o[2 * u + 1], Pl, V1);
            }
        }
        __syncthreads();
    }

    // ---- epilogue: normalize, split hi/lo, write [MTOT][DD] ----
    const int b = bh / HH;
    const int h = bh % HH;
#pragma unroll
    for (int rg = 0; rg < 2; rg++) {
        const float inv = 1.0f / l_[rg];
        const size_t rbase =
            (size_t)(b * TT + q0 + w * 16 + (lane >> 2) + rg * 8) * DD + h * 64;
#pragma unroll
        for (int u = 0; u < 8; u++) {
            const int d0 = u * 8 + (lane & 3) * 2;
            split_store(o[u][rg * 2] * inv, o[u][rg * 2 + 1] * inv,
                        oh_ + rbase + d0, ol_ + rbase + d0);
        }
    }
}

// ---------------------------------------------------------------------------
extern "C" void kernel_launch(void* const* d_in, const int* in_sizes, int n_in,
                              void* d_out, int out_size) {
    const float* x     = (const float*)d_in[0];
    const float* Wqkv  = (const float*)d_in[1];
    const float* Wproj = (const float*)d_in[2];
    const float* bproj = (const float*)d_in[3];
    float* out = (float*)d_out;

    __nv_bfloat16 *xhi, *xlo, *whi, *wlo, *phi, *plo, *ahi, *alo;
    __nv_bfloat16 *qh, *ql, *kh, *kl, *vh, *vl;
    cudaGetSymbolAddress((void**)&xhi, g_xhi);
    cudaGetSymbolAddress((void**)&xlo, g_xlo);
    cudaGetSymbolAddress((void**)&whi, g_whi);
    cudaGetSymbolAddress((void**)&wlo, g_wlo);
    cudaGetSymbolAddress((void**)&phi, g_phi);
    cudaGetSymbolAddress((void**)&plo, g_plo);
    cudaGetSymbolAddress((void**)&ahi, g_ahi);
    cudaGetSymbolAddress((void**)&alo, g_alo);
    cudaGetSymbolAddress((void**)&qh, g_qh);
    cudaGetSymbolAddress((void**)&ql, g_ql);
    cudaGetSymbolAddress((void**)&kh, g_kh);
    cudaGetSymbolAddress((void**)&kl, g_kl);
    cudaGetSymbolAddress((void**)&vh, g_vh);
    cudaGetSymbolAddress((void**)&vl, g_vl);

    cudaFuncSetAttribute(gemm_mma<0>,
                         cudaFuncAttributeMaxDynamicSharedMemorySize, GEMM_SMEM);
    cudaFuncSetAttribute(gemm_mma<1>,
                         cudaFuncAttributeMaxDynamicSharedMemorySize, GEMM_SMEM);
    cudaFuncSetAttribute(flash_mma,
                         cudaFuncAttributeMaxDynamicSharedMemorySize, FLASH_SMEM);

    // Split inputs to bf16 hi/lo
    {
        int n4 = MTOT * DD / 4;
        split_kernel<<<(n4 + 255) / 256, 256>>>(x, xhi, xlo, n4);
        n4 = THREE_D * DD / 4;
        split_kernel<<<(n4 + 255) / 256, 256>>>(Wqkv, whi, wlo, n4);
        n4 = DD * DD / 4;
        split_kernel<<<(n4 + 255) / 256, 256>>>(Wproj, phi, plo, n4);
    }

    // 1) QKV GEMM -> head-major bf16 hi/lo q/k/v (Q pre-scaled)
    {
        dim3 grid(THREE_D / 128, MTOT / 128);
        gemm_mma<1><<<grid, 256, GEMM_SMEM>>>(xhi, xlo, whi, wlo,
                                              nullptr, nullptr,
                                              qh, ql, kh, kl, vh, vl,
                                              MTOT, THREE_D, DD);
    }

    // 2) causal flash attention (tensor cores) -> ahi/alo
    {
        dim3 grid(TT / 128, BB * HH);
        flash_mma<<<grid, 256, FLASH_SMEM>>>(qh, ql, kh, kl, vh, vl, ahi, alo);
    }

    // 3) out = attn @ Wproj^T + bproj
    {
        dim3 grid(DD / 128, MTOT / 128);
        gemm_mma<0><<<grid, 256, GEMM_SMEM>>>(ahi, alo, phi, plo, out, bproj,
                                              nullptr, nullptr, nullptr,
                                              nullptr, nullptr, nullptr,
                                              MTOT, DD, DD);
    }
}

// round 6
// speedup vs baseline: 3.1053x; 1.6657x over previous
#include <cuda_runtime.h>
#include <cuda_bf16.h>
#include <math_constants.h>
#include <cstdint>

// Problem constants
#define BB 4
#define TT 2048
#define DD 768
#define HH 12
#define DHH 64
#define THREE_D 2304
#define MTOT (BB*TT)       // 8192
#define QSCALE 0.18033688011112042f   // 0.125 * log2(e)

// ---------------------------------------------------------------------------
// Scratch (device globals — no allocation allowed)
// ---------------------------------------------------------------------------
#define QKV_ELEMS ((size_t)BB * HH * TT * DHH)   // 6291456 per array
__device__ __nv_bfloat16 g_xhi[(size_t)MTOT * DD];
__device__ __nv_bfloat16 g_xlo[(size_t)MTOT * DD];
__device__ __nv_bfloat16 g_whi[(size_t)THREE_D * DD];
__device__ __nv_bfloat16 g_wlo[(size_t)THREE_D * DD];
__device__ __nv_bfloat16 g_phi[(size_t)DD * DD];
__device__ __nv_bfloat16 g_plo[(size_t)DD * DD];
__device__ __nv_bfloat16 g_ahi[(size_t)MTOT * DD];
__device__ __nv_bfloat16 g_alo[(size_t)MTOT * DD];
__device__ __nv_bfloat16 g_qh[QKV_ELEMS];
__device__ __nv_bfloat16 g_ql[QKV_ELEMS];
__device__ __nv_bfloat16 g_kh[QKV_ELEMS];
__device__ __nv_bfloat16 g_kl[QKV_ELEMS];
__device__ __nv_bfloat16 g_vh[QKV_ELEMS];
__device__ __nv_bfloat16 g_vl[QKV_ELEMS];

// ---------------------------------------------------------------------------
// PTX helpers (generic sm_80+ only — tcgen05 rejected: harness targets sm_103)
// ---------------------------------------------------------------------------
__device__ __forceinline__ uint32_t smem_u32(const void* p) {
    uint32_t a;
    asm("{ .reg .u64 t; cvta.to.shared.u64 t, %1; cvt.u32.u64 %0, t; }"
        : "=r"(a) : "l"(p));
    return a;
}
__device__ __forceinline__ void cp_async16(uint32_t dst, const void* src) {
    asm volatile("cp.async.cg.shared.global [%0], [%1], 16;"
                 :: "r"(dst), "l"(src));
}
__device__ __forceinline__ void cp_commit() {
    asm volatile("cp.async.commit_group;" ::: "memory");
}
template <int N>
__device__ __forceinline__ void cp_wait() {
    asm volatile("cp.async.wait_group %0;" :: "n"(N) : "memory");
}
__device__ __forceinline__ void ldsm4(uint32_t& r0, uint32_t& r1,
                                      uint32_t& r2, uint32_t& r3, uint32_t a) {
    asm volatile("ldmatrix.sync.aligned.m8n8.x4.shared.b16 {%0,%1,%2,%3}, [%4];"
                 : "=r"(r0), "=r"(r1), "=r"(r2), "=r"(r3) : "r"(a));
}
__device__ __forceinline__ void ldsm4t(uint32_t& r0, uint32_t& r1,
                                       uint32_t& r2, uint32_t& r3, uint32_t a) {
    asm volatile("ldmatrix.sync.aligned.m8n8.x4.trans.shared.b16 {%0,%1,%2,%3}, [%4];"
                 : "=r"(r0), "=r"(r1), "=r"(r2), "=r"(r3) : "r"(a));
}
__device__ __forceinline__ void mma_bf16(float* d, const uint32_t* a,
                                         const uint32_t* b) {
    asm volatile(
        "mma.sync.aligned.m16n8k16.row.col.f32.bf16.bf16.f32 "
        "{%0,%1,%2,%3}, {%4,%5,%6,%7}, {%8,%9}, {%0,%1,%2,%3};"
        : "+f"(d[0]), "+f"(d[1]), "+f"(d[2]), "+f"(d[3])
        : "r"(a[0]), "r"(a[1]), "r"(a[2]), "r"(a[3]), "r"(b[0]), "r"(b[1]));
}
__device__ __forceinline__ uint32_t pack_bf16x2(float lo, float hi) {
    uint32_t r;
    asm("cvt.rn.bf16x2.f32 %0, %1, %2;" : "=r"(r) : "f"(hi), "f"(lo));
    return r;
}
__device__ __forceinline__ float ex2(float x) {
    float y;
    asm("ex2.approx.ftz.f32 %0, %1;" : "=f"(y) : "f"(x));
    return y;
}
// trunc-split: hi = top-16-bits of two floats packed; residual exact
__device__ __forceinline__ void split_store(float v0, float v1,
                                            __nv_bfloat16* hi, __nv_bfloat16* lo) {
    uint32_t u0 = __float_as_uint(v0), u1 = __float_as_uint(v1);
    *(uint32_t*)hi = __byte_perm(u0, u1, 0x7632);
    float r0 = v0 - __uint_as_float(u0 & 0xffff0000u);
    float r1 = v1 - __uint_as_float(u1 & 0xffff0000u);
    *(uint32_t*)lo = pack_bf16x2(r0, r1);
}

// ---------------------------------------------------------------------------
// Split fp32 -> bf16 hi/lo (precompute for x, Wqkv, Wproj)
// ---------------------------------------------------------------------------
__global__ __launch_bounds__(256)
void split_kernel(const float* __restrict__ in, __nv_bfloat16* __restrict__ hi,
                  __nv_bfloat16* __restrict__ lo, int n4) {
    int i = blockIdx.x * blockDim.x + threadIdx.x;
    if (i >= n4) return;
    float4 v = ((const float4*)in)[i];
    float vv[4] = {v.x, v.y, v.z, v.w};
#pragma unroll
    for (int j = 0; j < 4; j += 2)
        split_store(vv[j], vv[j + 1], hi + (size_t)i * 4 + j, lo + (size_t)i * 4 + j);
}

// ---------------------------------------------------------------------------
// mma.sync GEMM: C[M,N] = A[M,K] @ B[N,K]^T, hi/lo bf16 inputs, 3-MMA split.
// CTA 128x128, 8 warps @ 32x64, BK=32, cp.async double-buffered.
// __launch_bounds__(256, 2): R5 regression root-cause — MODE 1 epilogue
// pushed regs to 129, dropping to 1 CTA/SM.  Force <=128 regs / 2 CTAs.
// MODE 0: fp32 out + bias.  MODE 1: QKV epilogue -> head-major bf16 hi/lo,
//         Q pre-scaled by QSCALE.
// ---------------------------------------------------------------------------
#define TILE_B    (128 * 40 * 2)          // 10240 B per tile (stride 40 bf16)
#define BUF_B     (4 * TILE_B)
#define GEMM_SMEM (2 * BUF_B)             // 81920 B

template <int MODE>
__global__ __launch_bounds__(256, 2)
void gemm_mma(const __nv_bfloat16* __restrict__ Ahi, const __nv_bfloat16* __restrict__ Alo,
              const __nv_bfloat16* __restrict__ Bhi, const __nv_bfloat16* __restrict__ Blo,
              float* __restrict__ C, const float* __restrict__ bias,
              __nv_bfloat16* __restrict__ qh, __nv_bfloat16* __restrict__ ql,
              __nv_bfloat16* __restrict__ kh, __nv_bfloat16* __restrict__ kl,
              __nv_bfloat16* __restrict__ vh, __nv_bfloat16* __restrict__ vl,
              int M, int N, int K) {
    extern __shared__ char smem[];
    const uint32_t sb = smem_u32(smem);
    const int tid = threadIdx.x;
    const int lane = tid & 31;
    const int warp = tid >> 5;
    const int wm = warp & 3;
    const int wn = warp >> 2;
    const int m0 = blockIdx.y * 128;
    const int n0 = blockIdx.x * 128;

    float acc[2][8][4];
#pragma unroll
    for (int f = 0; f < 2; f++)
#pragma unroll
        for (int j = 0; j < 8; j++)
#pragma unroll
            for (int e = 0; e < 4; e++) acc[f][j][e] = 0.f;

    const int nstage = K / 32;

#define ISSUE(s)                                                               \
    do {                                                                       \
        const int k0_ = (s) * 32;                                              \
        const uint32_t db_ = sb + ((s) & 1) * BUF_B;                           \
        _Pragma("unroll")                                                      \
        for (int tile = 0; tile < 4; tile++) {                                 \
            const __nv_bfloat16* src =                                         \
                (tile == 0) ? Ahi : (tile == 1) ? Alo : (tile == 2) ? Bhi : Blo; \
            const int base = (tile < 2) ? m0 : n0;                             \
            _Pragma("unroll")                                                  \
            for (int i = 0; i < 2; i++) {                                      \
                int c = tid + i * 256;                                         \
                int row = c >> 2, g = c & 3;                                   \
                cp_async16(db_ + tile * TILE_B + row * 80 + g * 16,            \
                           src + (size_t)(base + row) * K + k0_ + g * 8);      \
            }                                                                  \
        }                                                                      \
        cp_commit();                                                           \
    } while (0)

    ISSUE(0);

    for (int s = 0; s < nstage; s++) {
        if (s + 1 < nstage) { ISSUE(s + 1); cp_wait<1>(); }
        else                { cp_wait<0>(); }
        __syncthreads();

        const uint32_t bufb = sb + (s & 1) * BUF_B;
        const int q = lane >> 3;
#pragma unroll
        for (int kk = 0; kk < 32; kk += 16) {
            uint32_t Ah[2][4], Al[2][4], Bh[8][2], Bl[8][2];
#pragma unroll
            for (int f = 0; f < 2; f++) {
                uint32_t arow = wm * 32 + f * 16 + (lane & 15);
                uint32_t aoff = arow * 80 + (kk + (lane >> 4) * 8) * 2;
                ldsm4(Ah[f][0], Ah[f][1], Ah[f][2], Ah[f][3], bufb + aoff);
                ldsm4(Al[f][0], Al[f][1], Al[f][2], Al[f][3],
                      bufb + TILE_B + aoff);
            }
#pragma unroll
            for (int p = 0; p < 4; p++) {
                uint32_t brow = wn * 64 + p * 16 + (q >> 1) * 8 + (lane & 7);
                uint32_t boff = brow * 80 + (kk + (q & 1) * 8) * 2;
                ldsm4(Bh[2 * p][0], Bh[2 * p][1], Bh[2 * p + 1][0],
                      Bh[2 * p + 1][1], bufb + 2 * TILE_B + boff);
                ldsm4(Bl[2 * p][0], Bl[2 * p][1], Bl[2 * p + 1][0],
                      Bl[2 * p + 1][1], bufb + 3 * TILE_B + boff);
            }
#pragma unroll
            for (int f = 0; f < 2; f++)
#pragma unroll
                for (int j = 0; j < 8; j++) {
                    mma_bf16(acc[f][j], Ah[f], Bh[j]);
                    mma_bf16(acc[f][j], Ah[f], Bl[j]);
                    mma_bf16(acc[f][j], Al[f], Bh[j]);
                }
        }
        __syncthreads();
    }

    // epilogue
#pragma unroll
    for (int f = 0; f < 2; f++) {
        const int mrow = m0 + wm * 32 + f * 16 + (lane >> 2);
#pragma unroll
        for (int j = 0; j < 8; j++) {
            const int n = n0 + wn * 64 + j * 8 + (lane & 3) * 2;
            if (MODE == 0) {
                float2 v0, v1;
                v0.x = acc[f][j][0]; v0.y = acc[f][j][1];
                v1.x = acc[f][j][2]; v1.y = acc[f][j][3];
                float b0 = bias[n], b1 = bias[n + 1];
                v0.x += b0; v0.y += b1; v1.x += b0; v1.y += b1;
                *(float2*)&C[(size_t)mrow * N + n] = v0;
                *(float2*)&C[(size_t)(mrow + 8) * N + n] = v1;
            } else {
                const int type = n / DD;           // 0=q, 1=k, 2=v
                const int h = (n - type * DD) >> 6;
                const int d = n & 63;
                const float sc = (type == 0) ? QSCALE : 1.0f;
                __nv_bfloat16* dh = (type == 0) ? qh : (type == 1) ? kh : vh;
                __nv_bfloat16* dl = (type == 0) ? ql : (type == 1) ? kl : vl;
                const int bI = mrow >> 11;
                const int t = mrow & 2047;
                size_t idx = ((size_t)(bI * HH + h) * TT + t) * DHH + d;
                split_store(acc[f][j][0] * sc, acc[f][j][1] * sc, dh + idx, dl + idx);
                idx += (size_t)8 * DHH;            // row + 8, same head
                split_store(acc[f][j][2] * sc, acc[f][j][3] * sc, dh + idx, dl + idx);
            }
        }
    }
}

// ---------------------------------------------------------------------------
// Causal flash attention, mma.sync bf16 hi/lo.
// BM=128 (8 warps x 16 rows), BN=64, DH=64.  K/V double-buffered cp.async.
// Q fragments in registers.  Softmax in log2 domain (Q pre-scaled by QSCALE).
// Writes attn output directly as bf16 hi/lo [MTOT][DD].
// ---------------------------------------------------------------------------
#define KV_TILE_B  (64 * 144)             // 64 rows x 144 B (72 bf16, padded)
#define KV_STAGE   (4 * KV_TILE_B)        // 36864
#define FLASH_SMEM (2 * KV_STAGE)         // 73728

__global__ __launch_bounds__(256)
void flash_mma(const __nv_bfloat16* __restrict__ qh_, const __nv_bfloat16* __restrict__ ql_,
               const __nv_bfloat16* __restrict__ kh_, const __nv_bfloat16* __restrict__ kl_,
               const __nv_bfloat16* __restrict__ vh_, const __nv_bfloat16* __restrict__ vl_,
               __nv_bfloat16* __restrict__ oh_, __nv_bfloat16* __restrict__ ol_) {
    extern __shared__ char smem[];
    const uint32_t sb = smem_u32(smem);
    const int tid = threadIdx.x;
    const int lane = tid & 31;
    const int w = tid >> 5;
    const int qt = gridDim.x - 1 - blockIdx.x;   // heavy tiles first
    const int bh = blockIdx.y;
    const int q0 = qt * 128;
    const int nkt = 2 * qt + 2;
    const size_t hbase = (size_t)bh * TT * DHH;

#define FISSUE(s_)                                                             \
    do {                                                                       \
        const int k0_ = (s_) * 64;                                             \
        const uint32_t db_ = sb + ((s_) & 1) * KV_STAGE;                       \
        _Pragma("unroll")                                                      \
        for (int i = 0; i < 8; i++) {                                          \
            int c = tid + i * 256;                                             \
            int arr = c >> 9, cc = c & 511, row = cc >> 3, g = cc & 7;         \
            const __nv_bfloat16* src =                                         \
                (arr == 0) ? kh_ : (arr == 1) ? kl_ : (arr == 2) ? vh_ : vl_;  \
            cp_async16(db_ + arr * KV_TILE_B + row * 144 + g * 16,             \
                       src + hbase + (size_t)(k0_ + row) * DHH + g * 8);       \
        }                                                                      \
        cp_commit();                                                           \
    } while (0)

    FISSUE(0);

    // Q fragments (A-frags for 4 k-steps, hi+lo) — register resident
    uint32_t Qh[4][4], Ql[4][4];
    {
        const size_t qoff = hbase + (size_t)(q0 + w * 16) * DHH;
        const int r = lane >> 2;
        const int c = (lane & 3) * 2;
#pragma unroll
        for (int kk = 0; kk < 4; kk++) {
            const int cb = c + kk * 16;
            Qh[kk][0] = *(const uint32_t*)(qh_ + qoff + r * 64 + cb);
            Qh[kk][1] = *(const uint32_t*)(qh_ + qoff + (r + 8) * 64 + cb);
            Qh[kk][2] = *(const uint32_t*)(qh_ + qoff + r * 64 + cb + 8);
            Qh[kk][3] = *(const uint32_t*)(qh_ + qoff + (r + 8) * 64 + cb + 8);
            Ql[kk][0] = *(const uint32_t*)(ql_ + qoff + r * 64 + cb);
            Ql[kk][1] = *(const uint32_t*)(ql_ + qoff + (r + 8) * 64 + cb);
            Ql[kk][2] = *(const uint32_t*)(ql_ + qoff + r * 64 + cb + 8);
            Ql[kk][3] = *(const uint32_t*)(ql_ + qoff + (r + 8) * 64 + cb + 8);
        }
    }

    float m_[2] = {-CUDART_INF_F, -CUDART_INF_F};
    float l_[2] = {0.f, 0.f};
    float o[8][4];
#pragma unroll
    for (int j = 0; j < 8; j++)
#pragma unroll
        for (int e = 0; e < 4; e++) o[j][e] = 0.f;

    for (int kt = 0; kt < nkt; kt++) {
        if (kt + 1 < nkt) { FISSUE(kt + 1); cp_wait<1>(); }
        else              { cp_wait<0>(); }
        __syncthreads();
        const uint32_t buf = sb + (kt & 1) * KV_STAGE;

        // ---- S = Q K^T ----
        float s[8][4];
#pragma unroll
        for (int j = 0; j < 8; j++)
#pragma unroll
            for (int e = 0; e < 4; e++) s[j][e] = 0.f;

        const int qg = lane >> 3;
#pragma unroll
        for (int kk = 0; kk < 4; kk++) {
#pragma unroll
            for (int p = 0; p < 4; p++) {
                const uint32_t boff =
                    (uint32_t)((p * 16 + (qg >> 1) * 8 + (lane & 7)) * 144 +
                               (kk * 16 + (qg & 1) * 8) * 2);
                uint32_t B0[2], B1[2], C0[2], C1[2];
                ldsm4(B0[0], B0[1], B1[0], B1[1], buf + boff);
                ldsm4(C0[0], C0[1], C1[0], C1[1], buf + KV_TILE_B + boff);
                mma_bf16(s[2 * p],     Qh[kk], B0);
                mma_bf16(s[2 * p],     Qh[kk], C0);
                mma_bf16(s[2 * p],     Ql[kk], B0);
                mma_bf16(s[2 * p + 1], Qh[kk], B1);
                mma_bf16(s[2 * p + 1], Qh[kk], C1);
                mma_bf16(s[2 * p + 1], Ql[kk], B1);
            }
        }

        // ---- causal mask (only near-diagonal tiles) ----
        const int k0 = kt * 64;
        if (k0 + 63 > q0 + w * 16) {
            const int qr0 = q0 + w * 16 + (lane >> 2);
#pragma unroll
            for (int j = 0; j < 8; j++) {
                const int cb = k0 + j * 8 + (lane & 3) * 2;
#pragma unroll
                for (int e = 0; e < 4; e++) {
                    const int col = cb + (e & 1);
                    const int qr = qr0 + ((e >> 1) << 3);
                    if (col > qr) s[j][e] = -CUDART_INF_F;
                }
            }
        }

        // ---- online softmax (log2 domain) ----
#pragma unroll
        for (int rg = 0; rg < 2; rg++) {
            float mx = s[0][rg * 2];
#pragma unroll
            for (int j = 0; j < 8; j++)
                mx = fmaxf(mx, fmaxf(s[j][rg * 2], s[j][rg * 2 + 1]));
            mx = fmaxf(mx, __shfl_xor_sync(0xffffffffu, mx, 1));
            mx = fmaxf(mx, __shfl_xor_sync(0xffffffffu, mx, 2));
            const float mn = fmaxf(m_[rg], mx);
            const float al = ex2(m_[rg] - mn);
            float sum = 0.f;
#pragma unroll
            for (int j = 0; j < 8; j++) {
                float p0 = ex2(s[j][rg * 2] - mn);
                float p1 = ex2(s[j][rg * 2 + 1] - mn);
                s[j][rg * 2] = p0; s[j][rg * 2 + 1] = p1;
                sum += p0 + p1;
            }
            sum += __shfl_xor_sync(0xffffffffu, sum, 1);
            sum += __shfl_xor_sync(0xffffffffu, sum, 2);
            l_[rg] = l_[rg] * al + sum;
            m_[rg] = mn;
#pragma unroll
            for (int j = 0; j < 8; j++) {
                o[j][rg * 2] *= al;
                o[j][rg * 2 + 1] *= al;
            }
        }

        // ---- O += P V ----
#pragma unroll
        for (int t = 0; t < 4; t++) {
            uint32_t Ph[4], Pl[4];
#pragma unroll
            for (int idx = 0; idx < 4; idx++) {
                const float v0 = s[2 * t + (idx >> 1)][(idx & 1) * 2 + 0];
                const float v1 = s[2 * t + (idx >> 1)][(idx & 1) * 2 + 1];
                const uint32_t u0 = __float_as_uint(v0);
                const uint32_t u1 = __float_as_uint(v1);
                Ph[idx] = __byte_perm(u0, u1, 0x7632);
                const float r0 = v0 - __uint_as_float(u0 & 0xffff0000u);
                const float r1 = v1 - __uint_as_float(u1 & 0xffff0000u);
                Pl[idx] = pack_bf16x2(r0, r1);
            }
            const int vrow = t * 16 + (lane & 7) + ((lane >> 3) & 1) * 8;
            const int vcb = (lane >> 4) * 8;
#pragma unroll
            for (int u = 0; u < 4; u++) {
                const uint32_t a =
                    buf + 2 * KV_TILE_B + vrow * 144 + (u * 16 + vcb) * 2;
                uint32_t V0[2], V1[2], W0[2], W1[2];
                ldsm4t(V0[0], V0[1], V1[0], V1[1], a);
                ldsm4t(W0[0], W0[1], W1[0], W1[1], a + KV_TILE_B);
                mma_bf16(o[2 * u],     Ph, V0);
                mma_bf16(o[2 * u],     Ph, W0);
                mma_bf16(o[2 * u],     Pl, V0);
                mma_bf16(o[2 * u + 1], Ph, V1);
                mma_bf16(o[2 * u + 1], Ph, W1);
                mma_bf16(o[2 * u + 1], Pl, V1);
            }
        }
        __syncthreads();
    }

    // ---- epilogue: normalize, split hi/lo, write [MTOT][DD] ----
    const int b = bh / HH;
    const int h = bh % HH;
#pragma unroll
    for (int rg = 0; rg < 2; rg++) {
        const float inv = 1.0f / l_[rg];
        const size_t rbase =
            (size_t)(b * TT + q0 + w * 16 + (lane >> 2) + rg * 8) * DD + h * 64;
#pragma unroll
        for (int u = 0; u < 8; u++) {
            const int d0 = u * 8 + (lane & 3) * 2;
            split_store(o[u][rg * 2] * inv, o[u][rg * 2 + 1] * inv,
                        oh_ + rbase + d0, ol_ + rbase + d0);
        }
    }
}

// ---------------------------------------------------------------------------
extern "C" void kernel_launch(void* const* d_in, const int* in_sizes, int n_in,
                              void* d_out, int out_size) {
    const float* x     = (const float*)d_in[0];
    const float* Wqkv  = (const float*)d_in[1];
    const float* Wproj = (const float*)d_in[2];
    const float* bproj = (const float*)d_in[3];
    float* out = (float*)d_out;

    __nv_bfloat16 *xhi, *xlo, *whi, *wlo, *phi, *plo, *ahi, *alo;
    __nv_bfloat16 *qh, *ql, *kh, *kl, *vh, *vl;
    cudaGetSymbolAddress((void**)&xhi, g_xhi);
    cudaGetSymbolAddress((void**)&xlo, g_xlo);
    cudaGetSymbolAddress((void**)&whi, g_whi);
    cudaGetSymbolAddress((void**)&wlo, g_wlo);
    cudaGetSymbolAddress((void**)&phi, g_phi);
    cudaGetSymbolAddress((void**)&plo, g_plo);
    cudaGetSymbolAddress((void**)&ahi, g_ahi);
    cudaGetSymbolAddress((void**)&alo, g_alo);
    cudaGetSymbolAddress((void**)&qh, g_qh);
    cudaGetSymbolAddress((void**)&ql, g_ql);
    cudaGetSymbolAddress((void**)&kh, g_kh);
    cudaGetSymbolAddress((void**)&kl, g_kl);
    cudaGetSymbolAddress((void**)&vh, g_vh);
    cudaGetSymbolAddress((void**)&vl, g_vl);

    cudaFuncSetAttribute(gemm_mma<0>,
                         cudaFuncAttributeMaxDynamicSharedMemorySize, GEMM_SMEM);
    cudaFuncSetAttribute(gemm_mma<1>,
                         cudaFuncAttributeMaxDynamicSharedMemorySize, GEMM_SMEM);
    cudaFuncSetAttribute(flash_mma,
                         cudaFuncAttributeMaxDynamicSharedMemorySize, FLASH_SMEM);

    // Split inputs to bf16 hi/lo
    {
        int n4 = MTOT * DD / 4;
        split_kernel<<<(n4 + 255) / 256, 256>>>(x, xhi, xlo, n4);
        n4 = THREE_D * DD / 4;
        split_kernel<<<(n4 + 255) / 256, 256>>>(Wqkv, whi, wlo, n4);
        n4 = DD * DD / 4;
        split_kernel<<<(n4 + 255) / 256, 256>>>(Wproj, phi, plo, n4);
    }

    // 1) QKV GEMM -> head-major bf16 hi/lo q/k/v (Q pre-scaled)
    {
        dim3 grid(THREE_D / 128, MTOT / 128);
        gemm_mma<1><<<grid, 256, GEMM_SMEM>>>(xhi, xlo, whi, wlo,
                                              nullptr, nullptr,
                                              qh, ql, kh, kl, vh, vl,
                                              MTOT, THREE_D, DD);
    }

    // 2) causal flash attention (tensor cores) -> ahi/alo
    {
        dim3 grid(TT / 128, BB * HH);
        flash_mma<<<grid, 256, FLASH_SMEM>>>(qh, ql, kh, kl, vh, vl, ahi, alo);
    }

    // 3) out = attn @ Wproj^T + bproj
    {
        dim3 grid(DD / 128, MTOT / 128);
        gemm_mma<0><<<grid, 256, GEMM_SMEM>>>(ahi, alo, phi, plo, out, bproj,
                                              nullptr, nullptr, nullptr,
                                              nullptr, nullptr, nullptr,
                                              MTOT, DD, DD);
    }
}

// round 9
// speedup vs baseline: 4.1943x; 1.3507x over previous
#include <cuda_runtime.h>
#include <cuda_fp16.h>
#include <math_constants.h>
#include <cstdint>

// Problem constants
#define BB 4
#define TT 2048
#define DD 768
#define HH 12
#define DHH 64
#define THREE_D 2304
#define MTOT (BB*TT)       // 8192
#define QSCALE 0.18033688011112042f   // 0.125 * log2(e)

// ---------------------------------------------------------------------------
// Scratch (device globals — no allocation allowed).  fp16 2-term scheme:
// activations single fp16, weights/stationary side fp16 hi/lo pair.
// ---------------------------------------------------------------------------
#define QKV_ELEMS ((size_t)BB * HH * TT * DHH)
__device__ __half g_xh[(size_t)MTOT * DD];
__device__ __half g_wh[(size_t)THREE_D * DD];
__device__ __half g_wl[(size_t)THREE_D * DD];
__device__ __half g_ph[(size_t)DD * DD];
__device__ __half g_pl[(size_t)DD * DD];
__device__ __half g_ah[(size_t)MTOT * DD];
__device__ __half g_qh[QKV_ELEMS];
__device__ __half g_kh[QKV_ELEMS];
__device__ __half g_kl[QKV_ELEMS];
__device__ __half g_vh[QKV_ELEMS];
__device__ __half g_vl[QKV_ELEMS];

// ---------------------------------------------------------------------------
// PTX helpers (generic sm_80+ only — tcgen05 rejected: harness targets sm_103)
// ---------------------------------------------------------------------------
__device__ __forceinline__ uint32_t smem_u32(const void* p) {
    uint32_t a;
    asm("{ .reg .u64 t; cvta.to.shared.u64 t, %1; cvt.u32.u64 %0, t; }"
        : "=r"(a) : "l"(p));
    return a;
}
__device__ __forceinline__ void cp_async16(uint32_t dst, const void* src) {
    asm volatile("cp.async.cg.shared.global [%0], [%1], 16;"
                 :: "r"(dst), "l"(src));
}
__device__ __forceinline__ void cp_commit() {
    asm volatile("cp.async.commit_group;" ::: "memory");
}
template <int N>
__device__ __forceinline__ void cp_wait() {
    asm volatile("cp.async.wait_group %0;" :: "n"(N) : "memory");
}
__device__ __forceinline__ void ldsm4(uint32_t& r0, uint32_t& r1,
                                      uint32_t& r2, uint32_t& r3, uint32_t a) {
    asm volatile("ldmatrix.sync.aligned.m8n8.x4.shared.b16 {%0,%1,%2,%3}, [%4];"
                 : "=r"(r0), "=r"(r1), "=r"(r2), "=r"(r3) : "r"(a));
}
__device__ __forceinline__ void ldsm4t(uint32_t& r0, uint32_t& r1,
                                       uint32_t& r2, uint32_t& r3, uint32_t a) {
    asm volatile("ldmatrix.sync.aligned.m8n8.x4.trans.shared.b16 {%0,%1,%2,%3}, [%4];"
                 : "=r"(r0), "=r"(r1), "=r"(r2), "=r"(r3) : "r"(a));
}
__device__ __forceinline__ void mma_f16(float* d, const uint32_t* a,
                                        const uint32_t* b) {
    asm volatile(
        "mma.sync.aligned.m16n8k16.row.col.f32.f16.f16.f32 "
        "{%0,%1,%2,%3}, {%4,%5,%6,%7}, {%8,%9}, {%0,%1,%2,%3};"
        : "+f"(d[0]), "+f"(d[1]), "+f"(d[2]), "+f"(d[3])
        : "r"(a[0]), "r"(a[1]), "r"(a[2]), "r"(a[3]), "r"(b[0]), "r"(b[1]));
}
// first elem -> low 16 bits (cvt: first src -> high)
__device__ __forceinline__ uint32_t pack_f16x2(float lo, float hi) {
    uint32_t r;
    asm("cvt.rn.f16x2.f32 %0, %1, %2;" : "=r"(r) : "f"(hi), "f"(lo));
    return r;
}
__device__ __forceinline__ float ex2(float x) {
    float y;
    asm("ex2.approx.ftz.f32 %0, %1;" : "=f"(y) : "f"(x));
    return y;
}
// fp16 hi/lo split store (rn hi + exact residual re-rounded)
__device__ __forceinline__ void split_store_h(float v0, float v1,
                                              __half* hp, __half* lp) {
    __half2 h = __floats2half2_rn(v0, v1);
    *(__half2*)hp = h;
    float2 f = __half22float2(h);
    *(__half2*)lp = __floats2half2_rn(v0 - f.x, v1 - f.y);
}

// ---------------------------------------------------------------------------
// Conversion kernels
// ---------------------------------------------------------------------------
__global__ __launch_bounds__(256)
void split1_kernel(const float* __restrict__ in, __half* __restrict__ h, int n4) {
    int i = blockIdx.x * blockDim.x + threadIdx.x;
    if (i >= n4) return;
    float4 v = ((const float4*)in)[i];
    ((__half2*)h)[i * 2 + 0] = __floats2half2_rn(v.x, v.y);
    ((__half2*)h)[i * 2 + 1] = __floats2half2_rn(v.z, v.w);
}
__global__ __launch_bounds__(256)
void split2_kernel(const float* __restrict__ in, __half* __restrict__ hi,
                   __half* __restrict__ lo, int n4) {
    int i = blockIdx.x * blockDim.x + threadIdx.x;
    if (i >= n4) return;
    float4 v = ((const float4*)in)[i];
    split_store_h(v.x, v.y, hi + (size_t)i * 4, lo + (size_t)i * 4);
    split_store_h(v.z, v.w, hi + (size_t)i * 4 + 2, lo + (size_t)i * 4 + 2);
}

// ---------------------------------------------------------------------------
// mma.sync GEMM: C[M,N] = A[M,K] @ B[N,K]^T.  A single fp16, B fp16 hi/lo.
// 2 MMAs per microtile (A*Bh + A*Bl).  CTA 128x128, 8 warps @ 32x64, BK=32,
// cp.async double-buffered, 3 smem tiles per stage.
// MODE 0: fp32 out + bias.  MODE 1: QKV epilogue -> head-major fp16
//         (q single, scaled by QSCALE; k,v hi/lo pairs).
// ---------------------------------------------------------------------------
#define TILE_B    (128 * 40 * 2)          // 10240 B (stride 40 halves = 80 B)
#define BUF_B     (3 * TILE_B)            // 30720 B
#define GEMM_SMEM (2 * BUF_B)             // 61440 B

template <int MODE>
__global__ __launch_bounds__(256, 2)
void gemm_mma(const __half* __restrict__ A, const __half* __restrict__ Bh,
              const __half* __restrict__ Bl,
              float* __restrict__ C, const float* __restrict__ bias,
              __half* __restrict__ qh, __half* __restrict__ kh,
              __half* __restrict__ kl, __half* __restrict__ vh,
              __half* __restrict__ vl, int M, int N, int K) {
    extern __shared__ char smem[];
    const uint32_t sb = smem_u32(smem);
    const int tid = threadIdx.x;
    const int lane = tid & 31;
    const int warp = tid >> 5;
    const int wm = warp & 3;
    const int wn = warp >> 2;
    const int m0 = blockIdx.y * 128;
    const int n0 = blockIdx.x * 128;

    float acc[2][8][4];
#pragma unroll
    for (int f = 0; f < 2; f++)
#pragma unroll
        for (int j = 0; j < 8; j++)
#pragma unroll
            for (int e = 0; e < 4; e++) acc[f][j][e] = 0.f;

    const int nstage = K / 32;

#define ISSUE(s)                                                               \
    do {                                                                       \
        const int k0_ = (s) * 32;                                              \
        const uint32_t db_ = sb + ((s) & 1) * BUF_B;                           \
        _Pragma("unroll")                                                      \
        for (int i = 0; i < 6; i++) {                                          \
            const int tile = i >> 1;                /* 0=A,1=Bh,2=Bl */        \
            const int cc = tid + (i & 1) * 256;     /* 0..511 */               \
            const int row = cc >> 2, g = cc & 3;                               \
            const __half* src = (tile == 0) ? A : (tile == 1) ? Bh : Bl;       \
            const int base = (tile == 0) ? m0 : n0;                            \
            cp_async16(db_ + tile * TILE_B + row * 80 + g * 16,                \
                       src + (size_t)(base + row) * K + k0_ + g * 8);          \
        }                                                                      \
        cp_commit();                                                           \
    } while (0)

    ISSUE(0);

    for (int s = 0; s < nstage; s++) {
        if (s + 1 < nstage) { ISSUE(s + 1); cp_wait<1>(); }
        else                { cp_wait<0>(); }
        __syncthreads();

        const uint32_t bufb = sb + (s & 1) * BUF_B;
        const int q = lane >> 3;
#pragma unroll
        for (int kk = 0; kk < 32; kk += 16) {
            uint32_t Af[2][4], Bhf[8][2], Blf[8][2];
#pragma unroll
            for (int f = 0; f < 2; f++) {
                uint32_t arow = wm * 32 + f * 16 + (lane & 15);
                uint32_t aoff = arow * 80 + (kk + (lane >> 4) * 8) * 2;
                ldsm4(Af[f][0], Af[f][1], Af[f][2], Af[f][3], bufb + aoff);
            }
#pragma unroll
            for (int p = 0; p < 4; p++) {
                uint32_t brow = wn * 64 + p * 16 + (q >> 1) * 8 + (lane & 7);
                uint32_t boff = brow * 80 + (kk + (q & 1) * 8) * 2;
                ldsm4(Bhf[2 * p][0], Bhf[2 * p][1], Bhf[2 * p + 1][0],
                      Bhf[2 * p + 1][1], bufb + TILE_B + boff);
                ldsm4(Blf[2 * p][0], Blf[2 * p][1], Blf[2 * p + 1][0],
                      Blf[2 * p + 1][1], bufb + 2 * TILE_B + boff);
            }
#pragma unroll
            for (int f = 0; f < 2; f++)
#pragma unroll
                for (int j = 0; j < 8; j++) {
                    mma_f16(acc[f][j], Af[f], Bhf[j]);
                    mma_f16(acc[f][j], Af[f], Blf[j]);
                }
        }
        __syncthreads();
    }

    // epilogue
#pragma unroll
    for (int f = 0; f < 2; f++) {
        const int mrow = m0 + wm * 32 + f * 16 + (lane >> 2);
#pragma unroll
        for (int j = 0; j < 8; j++) {
            const int n = n0 + wn * 64 + j * 8 + (lane & 3) * 2;
            if (MODE == 0) {
                float2 v0, v1;
                v0.x = acc[f][j][0]; v0.y = acc[f][j][1];
                v1.x = acc[f][j][2]; v1.y = acc[f][j][3];
                float b0 = bias[n], b1 = bias[n + 1];
                v0.x += b0; v0.y += b1; v1.x += b0; v1.y += b1;
                *(float2*)&C[(size_t)mrow * N + n] = v0;
                *(float2*)&C[(size_t)(mrow + 8) * N + n] = v1;
            } else {
                const int type = n / DD;           // 0=q, 1=k, 2=v
                const int h = (n - type * DD) >> 6;
                const int d = n & 63;
                const int bI = mrow >> 11;
                const int t = mrow & 2047;
                size_t idx = ((size_t)(bI * HH + h) * TT + t) * DHH + d;
                const size_t idx8 = idx + (size_t)8 * DHH;
                if (type == 0) {
                    *(__half2*)(qh + idx) =
                        __floats2half2_rn(acc[f][j][0] * QSCALE, acc[f][j][1] * QSCALE);
                    *(__half2*)(qh + idx8) =
                        __floats2half2_rn(acc[f][j][2] * QSCALE, acc[f][j][3] * QSCALE);
                } else {
                    __half* dh = (type == 1) ? kh : vh;
                    __half* dl = (type == 1) ? kl : vl;
                    split_store_h(acc[f][j][0], acc[f][j][1], dh + idx, dl + idx);
                    split_store_h(acc[f][j][2], acc[f][j][3], dh + idx8, dl + idx8);
                }
            }
        }
    }
}

// ---------------------------------------------------------------------------
// Causal flash attention, mma.sync fp16.  Q single (registers), K/V hi/lo.
// BM=128 (8 warps x 16 rows), BN=64.  2 MMAs per term.  2 CTAs/SM.
// Writes attn output directly as single fp16 [MTOT][DD].
// ---------------------------------------------------------------------------
#define KV_TILE_B  (64 * 144)             // 64 rows x 144 B (72 halves pad)
#define KV_STAGE   (4 * KV_TILE_B)        // 36864
#define FLASH_SMEM (2 * KV_STAGE)         // 73728

__global__ __launch_bounds__(256, 2)
void flash_mma(const __half* __restrict__ qh_, const __half* __restrict__ kh_,
               const __half* __restrict__ kl_, const __half* __restrict__ vh_,
               const __half* __restrict__ vl_, __half* __restrict__ ah_) {
    extern __shared__ char smem[];
    const uint32_t sb = smem_u32(smem);
    const int tid = threadIdx.x;
    const int lane = tid & 31;
    const int w = tid >> 5;
    const int qt = gridDim.x - 1 - blockIdx.x;   // heavy tiles first
    const int bh = blockIdx.y;
    const int q0 = qt * 128;
    const int nkt = 2 * qt + 2;
    const size_t hbase = (size_t)bh * TT * DHH;

#define FISSUE(s_)                                                             \
    do {                                                                       \
        const int k0_ = (s_) * 64;                                             \
        const uint32_t db_ = sb + ((s_) & 1) * KV_STAGE;                       \
        _Pragma("unroll")                                                      \
        for (int i = 0; i < 8; i++) {                                          \
            const int arr = i >> 1;                                            \
            const int cc = tid + (i & 1) * 256;     /* 0..511 */               \
            const int row = cc >> 3, g = cc & 7;                               \
            const __half* src =                                                \
                (arr == 0) ? kh_ : (arr == 1) ? kl_ : (arr == 2) ? vh_ : vl_;  \
            cp_async16(db_ + arr * KV_TILE_B + row * 144 + g * 16,             \
                       src + hbase + (size_t)(k0_ + row) * DHH + g * 8);       \
        }                                                                      \
        cp_commit();                                                           \
    } while (0)

    FISSUE(0);

    // Q fragments (A-frags for 4 k-steps) — single fp16, register resident
    uint32_t Qf[4][4];
    {
        const size_t qoff = hbase + (size_t)(q0 + w * 16) * DHH;
        const int r = lane >> 2;
        const int c = (lane & 3) * 2;
#pragma unroll
        for (int kk = 0; kk < 4; kk++) {
            const int cb = c + kk * 16;
            Qf[kk][0] = *(const uint32_t*)(qh_ + qoff + r * 64 + cb);
            Qf[kk][1] = *(const uint32_t*)(qh_ + qoff + (r + 8) * 64 + cb);
            Qf[kk][2] = *(const uint32_t*)(qh_ + qoff + r * 64 + cb + 8);
            Qf[kk][3] = *(const uint32_t*)(qh_ + qoff + (r + 8) * 64 + cb + 8);
        }
    }

    float m_[2] = {-CUDART_INF_F, -CUDART_INF_F};
    float l_[2] = {0.f, 0.f};
    float o[8][4];
#pragma unroll
    for (int j = 0; j < 8; j++)
#pragma unroll
        for (int e = 0; e < 4; e++) o[j][e] = 0.f;

    for (int kt = 0; kt < nkt; kt++) {
        if (kt + 1 < nkt) { FISSUE(kt + 1); cp_wait<1>(); }
        else              { cp_wait<0>(); }
        __syncthreads();
        const uint32_t buf = sb + (kt & 1) * KV_STAGE;

        // ---- S = Q K^T  (Qh*Kh + Qh*Kl) ----
        float s[8][4];
#pragma unroll
        for (int j = 0; j < 8; j++)
#pragma unroll
            for (int e = 0; e < 4; e++) s[j][e] = 0.f;

        const int qg = lane >> 3;
#pragma unroll
        for (int kk = 0; kk < 4; kk++) {
#pragma unroll
            for (int p = 0; p < 4; p++) {
                const uint32_t boff =
                    (uint32_t)((p * 16 + (qg >> 1) * 8 + (lane & 7)) * 144 +
                               (kk * 16 + (qg & 1) * 8) * 2);
                uint32_t B0[2], B1[2], C0[2], C1[2];
                ldsm4(B0[0], B0[1], B1[0], B1[1], buf + boff);
                ldsm4(C0[0], C0[1], C1[0], C1[1], buf + KV_TILE_B + boff);
                mma_f16(s[2 * p],     Qf[kk], B0);
                mma_f16(s[2 * p],     Qf[kk], C0);
                mma_f16(s[2 * p + 1], Qf[kk], B1);
                mma_f16(s[2 * p + 1], Qf[kk], C1);
            }
        }

        // ---- causal mask (only near-diagonal tiles) ----
        const int k0 = kt * 64;
        if (k0 + 63 > q0 + w * 16) {
            const int qr0 = q0 + w * 16 + (lane >> 2);
#pragma unroll
            for (int j = 0; j < 8; j++) {
                const int cb = k0 + j * 8 + (lane & 3) * 2;
#pragma unroll
                for (int e = 0; e < 4; e++) {
                    const int col = cb + (e & 1);
                    const int qr = qr0 + ((e >> 1) << 3);
                    if (col > qr) s[j][e] = -CUDART_INF_F;
                }
            }
        }

        // ---- online softmax (log2 domain) ----
#pragma unroll
        for (int rg = 0; rg < 2; rg++) {
            float mx = s[0][rg * 2];
#pragma unroll
            for (int j = 0; j < 8; j++)
                mx = fmaxf(mx, fmaxf(s[j][rg * 2], s[j][rg * 2 + 1]));
            mx = fmaxf(mx, __shfl_xor_sync(0xffffffffu, mx, 1));
            mx = fmaxf(mx, __shfl_xor_sync(0xffffffffu, mx, 2));
            const float mn = fmaxf(m_[rg], mx);
            const float al = ex2(m_[rg] - mn);
            float sum = 0.f;
#pragma unroll
            for (int j = 0; j < 8; j++) {
                float p0 = ex2(s[j][rg * 2] - mn);
                float p1 = ex2(s[j][rg * 2 + 1] - mn);
                s[j][rg * 2] = p0; s[j][rg * 2 + 1] = p1;
                sum += p0 + p1;
            }
            sum += __shfl_xor_sync(0xffffffffu, sum, 1);
            sum += __shfl_xor_sync(0xffffffffu, sum, 2);
            l_[rg] = l_[rg] * al + sum;
            m_[rg] = mn;
#pragma unroll
            for (int j = 0; j < 8; j++) {
                o[j][rg * 2] *= al;
                o[j][rg * 2 + 1] *= al;
            }
        }

        // ---- O += P V  (P single fp16; Ph*Vh + Ph*Vl) ----
#pragma unroll
        for (int t = 0; t < 4; t++) {
            uint32_t Ph[4];
#pragma unroll
            for (int idx = 0; idx < 4; idx++)
                Ph[idx] = pack_f16x2(s[2 * t + (idx >> 1)][(idx & 1) * 2 + 0],
                                     s[2 * t + (idx >> 1)][(idx & 1) * 2 + 1]);
            const int vrow = t * 16 + (lane & 7) + ((lane >> 3) & 1) * 8;
            const int vcb = (lane >> 4) * 8;
#pragma unroll
            for (int u = 0; u < 4; u++) {
                const uint32_t a =
                    buf + 2 * KV_TILE_B + vrow * 144 + (u * 16 + vcb) * 2;
                uint32_t V0[2], V1[2], W0[2], W1[2];
                ldsm4t(V0[0], V0[1], V1[0], V1[1], a);
                ldsm4t(W0[0], W0[1], W1[0], W1[1], a + KV_TILE_B);
                mma_f16(o[2 * u],     Ph, V0);
                mma_f16(o[2 * u],     Ph, W0);
                mma_f16(o[2 * u + 1], Ph, V1);
                mma_f16(o[2 * u + 1], Ph, W1);
            }
        }
        __syncthreads();
    }

    // ---- epilogue: normalize, write single fp16 [MTOT][DD] ----
    const int b = bh / HH;
    const int h = bh % HH;
#pragma unroll
    for (int rg = 0; rg < 2; rg++) {
        const float inv = 1.0f / l_[rg];
        const size_t rbase =
            (size_t)(b * TT + q0 + w * 16 + (lane >> 2) + rg * 8) * DD + h * 64;
#pragma unroll
        for (int u = 0; u < 8; u++) {
            const int d0 = u * 8 + (lane & 3) * 2;
            *(__half2*)(ah_ + rbase + d0) =
                __floats2half2_rn(o[u][rg * 2] * inv, o[u][rg * 2 + 1] * inv);
        }
    }
}

// ---------------------------------------------------------------------------
extern "C" void kernel_launch(void* const* d_in, const int* in_sizes, int n_in,
                              void* d_out, int out_size) {
    const float* x     = (const float*)d_in[0];
    const float* Wqkv  = (const float*)d_in[1];
    const float* Wproj = (const float*)d_in[2];
    const float* bproj = (const float*)d_in[3];
    float* out = (float*)d_out;

    __half *xh, *wh, *wl, *ph, *pl, *ah, *qh, *kh, *kl, *vh, *vl;
    cudaGetSymbolAddress((void**)&xh, g_xh);
    cudaGetSymbolAddress((void**)&wh, g_wh);
    cudaGetSymbolAddress((void**)&wl, g_wl);
    cudaGetSymbolAddress((void**)&ph, g_ph);
    cudaGetSymbolAddress((void**)&pl, g_pl);
    cudaGetSymbolAddress((void**)&ah, g_ah);
    cudaGetSymbolAddress((void**)&qh, g_qh);
    cudaGetSymbolAddress((void**)&kh, g_kh);
    cudaGetSymbolAddress((void**)&kl, g_kl);
    cudaGetSymbolAddress((void**)&vh, g_vh);
    cudaGetSymbolAddress((void**)&vl, g_vl);

    cudaFuncSetAttribute(gemm_mma<0>,
                         cudaFuncAttributeMaxDynamicSharedMemorySize, GEMM_SMEM);
    cudaFuncSetAttribute(gemm_mma<1>,
                         cudaFuncAttributeMaxDynamicSharedMemorySize, GEMM_SMEM);
    cudaFuncSetAttribute(flash_mma,
                         cudaFuncAttributeMaxDynamicSharedMemorySize, FLASH_SMEM);

    // Convert inputs
    {
        int n4 = MTOT * DD / 4;
        split1_kernel<<<(n4 + 255) / 256, 256>>>(x, xh, n4);
        n4 = THREE_D * DD / 4;
        split2_kernel<<<(n4 + 255) / 256, 256>>>(Wqkv, wh, wl, n4);
        n4 = DD * DD / 4;
        split2_kernel<<<(n4 + 255) / 256, 256>>>(Wproj, ph, pl, n4);
    }

    // 1) QKV GEMM -> head-major fp16 q (single, scaled) / k,v (hi/lo)
    {
        dim3 grid(THREE_D / 128, MTOT / 128);
        gemm_mma<1><<<grid, 256, GEMM_SMEM>>>(xh, wh, wl, nullptr, nullptr,
                                              qh, kh, kl, vh, vl,
                                              MTOT, THREE_D, DD);
    }

    // 2) causal flash attention -> ah (single fp16)
    {
        dim3 grid(TT / 128, BB * HH);
        flash_mma<<<grid, 256, FLASH_SMEM>>>(qh, kh, kl, vh, vl, ah);
    }

    // 3) out = attn @ Wproj^T + bproj
    {
        dim3 grid(DD / 128, MTOT / 128);
        gemm_mma<0><<<grid, 256, GEMM_SMEM>>>(ah, ph, pl, out, bproj,
                                              nullptr, nullptr, nullptr,
                                              nullptr, nullptr,
                                              MTOT, DD, DD);
    }
}

// round 13
// speedup vs baseline: 4.5087x; 1.0750x over previous
#include <cuda_runtime.h>
#include <cuda_fp16.h>
#include <math_constants.h>
#include <cstdint>

// Problem constants
#define BB 4
#define TT 2048
#define DD 768
#define HH 12
#define DHH 64
#define THREE_D 2304
#define MTOT (BB*TT)       // 8192
#define QSCALE 0.18033688011112042f   // 0.125 * log2(e)

// ---------------------------------------------------------------------------
// Scratch (device globals — no allocation allowed).  fp16 2-term scheme:
// activations single fp16, weights/stationary side fp16 hi/lo pair.
// ---------------------------------------------------------------------------
#define QKV_ELEMS ((size_t)BB * HH * TT * DHH)
__device__ __half g_xh[(size_t)MTOT * DD];
__device__ __half g_wh[(size_t)THREE_D * DD];
__device__ __half g_wl[(size_t)THREE_D * DD];
__device__ __half g_ph[(size_t)DD * DD];
__device__ __half g_pl[(size_t)DD * DD];
__device__ __half g_ah[(size_t)MTOT * DD];
__device__ __half g_qh[QKV_ELEMS];
__device__ __half g_kh[QKV_ELEMS];
__device__ __half g_kl[QKV_ELEMS];
__device__ __half g_vh[QKV_ELEMS];
__device__ __half g_vl[QKV_ELEMS];

// ---------------------------------------------------------------------------
// PTX helpers (generic sm_80+ only — tcgen05 rejected: harness targets sm_103)
// ---------------------------------------------------------------------------
__device__ __forceinline__ uint32_t smem_u32(const void* p) {
    uint32_t a;
    asm("{ .reg .u64 t; cvta.to.shared.u64 t, %1; cvt.u32.u64 %0, t; }"
        : "=r"(a) : "l"(p));
    return a;
}
__device__ __forceinline__ void cp_async16(uint32_t dst, const void* src) {
    asm volatile("cp.async.cg.shared.global [%0], [%1], 16;"
                 :: "r"(dst), "l"(src));
}
__device__ __forceinline__ void cp_commit() {
    asm volatile("cp.async.commit_group;" ::: "memory");
}
template <int N>
__device__ __forceinline__ void cp_wait() {
    asm volatile("cp.async.wait_group %0;" :: "n"(N) : "memory");
}
__device__ __forceinline__ void ldsm4(uint32_t& r0, uint32_t& r1,
                                      uint32_t& r2, uint32_t& r3, uint32_t a) {
    asm volatile("ldmatrix.sync.aligned.m8n8.x4.shared.b16 {%0,%1,%2,%3}, [%4];"
                 : "=r"(r0), "=r"(r1), "=r"(r2), "=r"(r3) : "r"(a));
}
__device__ __forceinline__ void ldsm4t(uint32_t& r0, uint32_t& r1,
                                       uint32_t& r2, uint32_t& r3, uint32_t a) {
    asm volatile("ldmatrix.sync.aligned.m8n8.x4.trans.shared.b16 {%0,%1,%2,%3}, [%4];"
                 : "=r"(r0), "=r"(r1), "=r"(r2), "=r"(r3) : "r"(a));
}
__device__ __forceinline__ void mma_f16(float* d, const uint32_t* a,
                                        const uint32_t* b) {
    asm volatile(
        "mma.sync.aligned.m16n8k16.row.col.f32.f16.f16.f32 "
        "{%0,%1,%2,%3}, {%4,%5,%6,%7}, {%8,%9}, {%0,%1,%2,%3};"
        : "+f"(d[0]), "+f"(d[1]), "+f"(d[2]), "+f"(d[3])
        : "r"(a[0]), "r"(a[1]), "r"(a[2]), "r"(a[3]), "r"(b[0]), "r"(b[1]));
}
// first elem -> low 16 bits (cvt: first src -> high)
__device__ __forceinline__ uint32_t pack_f16x2(float lo, float hi) {
    uint32_t r;
    asm("cvt.rn.f16x2.f32 %0, %1, %2;" : "=r"(r) : "f"(hi), "f"(lo));
    return r;
}
__device__ __forceinline__ float ex2(float x) {
    float y;
    asm("ex2.approx.ftz.f32 %0, %1;" : "=f"(y) : "f"(x));
    return y;
}
// fp16 hi/lo split store (rn hi + exact residual re-rounded)
__device__ __forceinline__ void split_store_h(float v0, float v1,
                                              __half* hp, __half* lp) {
    __half2 h = __floats2half2_rn(v0, v1);
    *(__half2*)hp = h;
    float2 f = __half22float2(h);
    *(__half2*)lp = __floats2half2_rn(v0 - f.x, v1 - f.y);
}

// ---------------------------------------------------------------------------
// Conversion kernels
// ---------------------------------------------------------------------------
__global__ __launch_bounds__(256)
void split1_kernel(const float* __restrict__ in, __half* __restrict__ h, int n4) {
    int i = blockIdx.x * blockDim.x + threadIdx.x;
    if (i >= n4) return;
    float4 v = ((const float4*)in)[i];
    ((__half2*)h)[i * 2 + 0] = __floats2half2_rn(v.x, v.y);
    ((__half2*)h)[i * 2 + 1] = __floats2half2_rn(v.z, v.w);
}
__global__ __launch_bounds__(256)
void split2_kernel(const float* __restrict__ in, __half* __restrict__ hi,
                   __half* __restrict__ lo, int n4) {
    int i = blockIdx.x * blockDim.x + threadIdx.x;
    if (i >= n4) return;
    float4 v = ((const float4*)in)[i];
    split_store_h(v.x, v.y, hi + (size_t)i * 4, lo + (size_t)i * 4);
    split_store_h(v.z, v.w, hi + (size_t)i * 4 + 2, lo + (size_t)i * 4 + 2);
}

// ---------------------------------------------------------------------------
// mma.sync GEMM: C[M,N] = A[M,K] @ B[N,K]^T.  A single fp16, B fp16 hi/lo.
// CTA 128x128, 4 warps @ 64x64 warp tile (128 threads) — B-fragment reuse
// doubled vs 32x64 tiling (96 B ldsm traffic / MMA vs 160).  BK=32,
// cp.async double-buffered, 3 smem tiles per stage.  2 CTAs/SM.
// MODE 0: fp32 out + bias.  MODE 1: QKV epilogue -> head-major fp16
//         (q single, scaled by QSCALE; k,v hi/lo pairs).
// ---------------------------------------------------------------------------
#define TILE_B    (128 * 40 * 2)          // 10240 B (stride 40 halves = 80 B)
#define BUF_B     (3 * TILE_B)            // 30720 B
#define GEMM_SMEM (2 * BUF_B)             // 61440 B

template <int MODE>
__global__ __launch_bounds__(128, 2)
void gemm_mma(const __half* __restrict__ A, const __half* __restrict__ Bh,
              const __half* __restrict__ Bl,
              float* __restrict__ C, const float* __restrict__ bias,
              __half* __restrict__ qh, __half* __restrict__ kh,
              __half* __restrict__ kl, __half* __restrict__ vh,
              __half* __restrict__ vl, int M, int N, int K) {
    extern __shared__ char smem[];
    const uint32_t sb = smem_u32(smem);
    const int tid = threadIdx.x;
    const int lane = tid & 31;
    const int warp = tid >> 5;
    const int wm = warp & 1;       // rows wm*64
    const int wn = warp >> 1;      // cols wn*64
    const int m0 = blockIdx.y * 128;
    const int n0 = blockIdx.x * 128;

    float acc[4][8][4];
#pragma unroll
    for (int f = 0; f < 4; f++)
#pragma unroll
        for (int j = 0; j < 8; j++)
#pragma unroll
            for (int e = 0; e < 4; e++) acc[f][j][e] = 0.f;

    const int nstage = K / 32;

#define ISSUE(s)                                                               \
    do {                                                                       \
        const int k0_ = (s) * 32;                                              \
        const uint32_t db_ = sb + ((s) & 1) * BUF_B;                           \
        _Pragma("unroll")                                                      \
        for (int i = 0; i < 12; i++) {                                         \
            const int tile = i >> 2;                /* 0=A,1=Bh,2=Bl */        \
            const int cc = tid + (i & 3) * 128;     /* 0..511 */               \
            const int row = cc >> 2, g = cc & 3;                               \
            const __half* src = (tile == 0) ? A : (tile == 1) ? Bh : Bl;       \
            const int base = (tile == 0) ? m0 : n0;                            \
            cp_async16(db_ + tile * TILE_B + row * 80 + g * 16,                \
                       src + (size_t)(base + row) * K + k0_ + g * 8);          \
        }                                                                      \
        cp_commit();                                                           \
    } while (0)

    ISSUE(0);

    for (int s = 0; s < nstage; s++) {
        if (s + 1 < nstage) { ISSUE(s + 1); cp_wait<1>(); }
        else                { cp_wait<0>(); }
        __syncthreads();

        const uint32_t bufb = sb + (s & 1) * BUF_B;
        const int q = lane >> 3;
#pragma unroll
        for (int kk = 0; kk < 32; kk += 16) {
            uint32_t Af[4][4], Bhf[8][2], Blf[8][2];
#pragma unroll
            for (int f = 0; f < 4; f++) {
                uint32_t arow = wm * 64 + f * 16 + (lane & 15);
                uint32_t aoff = arow * 80 + (kk + (lane >> 4) * 8) * 2;
                ldsm4(Af[f][0], Af[f][1], Af[f][2], Af[f][3], bufb + aoff);
            }
#pragma unroll
            for (int p = 0; p < 4; p++) {
                uint32_t brow = wn * 64 + p * 16 + (q >> 1) * 8 + (lane & 7);
                uint32_t boff = brow * 80 + (kk + (q & 1) * 8) * 2;
                ldsm4(Bhf[2 * p][0], Bhf[2 * p][1], Bhf[2 * p + 1][0],
                      Bhf[2 * p + 1][1], bufb + TILE_B + boff);
                ldsm4(Blf[2 * p][0], Blf[2 * p][1], Blf[2 * p + 1][0],
                      Blf[2 * p + 1][1], bufb + 2 * TILE_B + boff);
            }
#pragma unroll
            for (int f = 0; f < 4; f++)
#pragma unroll
                for (int j = 0; j < 8; j++) {
                    mma_f16(acc[f][j], Af[f], Bhf[j]);
                    mma_f16(acc[f][j], Af[f], Blf[j]);
                }
        }
        __syncthreads();
    }

    // epilogue
#pragma unroll
    for (int f = 0; f < 4; f++) {
        const int mrow = m0 + wm * 64 + f * 16 + (lane >> 2);
#pragma unroll
        for (int j = 0; j < 8; j++) {
            const int n = n0 + wn * 64 + j * 8 + (lane & 3) * 2;
            if (MODE == 0) {
                float2 v0, v1;
                v0.x = acc[f][j][0]; v0.y = acc[f][j][1];
                v1.x = acc[f][j][2]; v1.y = acc[f][j][3];
                float b0 = bias[n], b1 = bias[n + 1];
                v0.x += b0; v0.y += b1; v1.x += b0; v1.y += b1;
                *(float2*)&C[(size_t)mrow * N + n] = v0;
                *(float2*)&C[(size_t)(mrow + 8) * N + n] = v1;
            } else {
                const int type = n / DD;           // 0=q, 1=k, 2=v
                const int h = (n - type * DD) >> 6;
                const int d = n & 63;
                const int bI = mrow >> 11;
                const int t = mrow & 2047;
                size_t idx = ((size_t)(bI * HH + h) * TT + t) * DHH + d;
                const size_t idx8 = idx + (size_t)8 * DHH;
                if (type == 0) {
                    *(__half2*)(qh + idx) =
                        __floats2half2_rn(acc[f][j][0] * QSCALE, acc[f][j][1] * QSCALE);
                    *(__half2*)(qh + idx8) =
                        __floats2half2_rn(acc[f][j][2] * QSCALE, acc[f][j][3] * QSCALE);
                } else {
                    __half* dh = (type == 1) ? kh : vh;
                    __half* dl = (type == 1) ? kl : vl;
                    split_store_h(acc[f][j][0], acc[f][j][1], dh + idx, dl + idx);
                    split_store_h(acc[f][j][2], acc[f][j][3], dh + idx8, dl + idx8);
                }
            }
        }
    }
}

// ---------------------------------------------------------------------------
// Causal flash attention, mma.sync fp16.  Q single (registers), K/V hi/lo.
// BM=128 = 4 warps x 32 rows (128 threads) — K/V fragment reuse doubled.
// BN=64.  Softmax log2 domain.  Writes attn as single fp16 [MTOT][DD].
// ---------------------------------------------------------------------------
#define KV_TILE_B  (64 * 144)             // 64 rows x 144 B (72 halves pad)
#define KV_STAGE   (4 * KV_TILE_B)        // 36864
#define FLASH_SMEM (2 * KV_STAGE)         // 73728

__global__ __launch_bounds__(128, 2)
void flash_mma(const __half* __restrict__ qh_, const __half* __restrict__ kh_,
               const __half* __restrict__ kl_, const __half* __restrict__ vh_,
               const __half* __restrict__ vl_, __half* __restrict__ ah_) {
    extern __shared__ char smem[];
    const uint32_t sb = smem_u32(smem);
    const int tid = threadIdx.x;
    const int lane = tid & 31;
    const int w = tid >> 5;                      // 4 warps, 32 rows each
    const int qt = gridDim.x - 1 - blockIdx.x;   // heavy tiles first
    const int bh = blockIdx.y;
    const int q0 = qt * 128;
    const int nkt = 2 * qt + 2;
    const size_t hbase = (size_t)bh * TT * DHH;

#define FISSUE(s_)                                                             \
    do {                                                                       \
        const int k0_ = (s_) * 64;                                             \
        const uint32_t db_ = sb + ((s_) & 1) * KV_STAGE;                       \
        _Pragma("unroll")                                                      \
        for (int i = 0; i < 16; i++) {                                         \
            const int arr = i >> 2;                                            \
            const int cc = tid + (i & 3) * 128;     /* 0..511 */               \
            const int row = cc >> 3, g = cc & 7;                               \
            const __half* src =                                                \
                (arr == 0) ? kh_ : (arr == 1) ? kl_ : (arr == 2) ? vh_ : vl_;  \
            cp_async16(db_ + arr * KV_TILE_B + row * 144 + g * 16,             \
                       src + hbase + (size_t)(k0_ + row) * DHH + g * 8);       \
        }                                                                      \
        cp_commit();                                                           \
    } while (0)

    FISSUE(0);

    // Q fragments: 2 m16-tiles x 4 k-steps, single fp16, register resident
    uint32_t Qf[4][2][4];
    {
        const int r = lane >> 2;
        const int c = (lane & 3) * 2;
#pragma unroll
        for (int f = 0; f < 2; f++) {
            const size_t qoff = hbase + (size_t)(q0 + w * 32 + f * 16) * DHH;
#pragma unroll
            for (int kk = 0; kk < 4; kk++) {
                const int cb = c + kk * 16;
                Qf[kk][f][0] = *(const uint32_t*)(qh_ + qoff + r * 64 + cb);
                Qf[kk][f][1] = *(const uint32_t*)(qh_ + qoff + (r + 8) * 64 + cb);
                Qf[kk][f][2] = *(const uint32_t*)(qh_ + qoff + r * 64 + cb + 8);
                Qf[kk][f][3] = *(const uint32_t*)(qh_ + qoff + (r + 8) * 64 + cb + 8);
            }
        }
    }

    float m_[2][2], l_[2][2];
#pragma unroll
    for (int f = 0; f < 2; f++)
#pragma unroll
        for (int rg = 0; rg < 2; rg++) { m_[f][rg] = -CUDART_INF_F; l_[f][rg] = 0.f; }
    float o[2][8][4];
#pragma unroll
    for (int f = 0; f < 2; f++)
#pragma unroll
        for (int j = 0; j < 8; j++)
#pragma unroll
            for (int e = 0; e < 4; e++) o[f][j][e] = 0.f;

    for (int kt = 0; kt < nkt; kt++) {
        if (kt + 1 < nkt) { FISSUE(kt + 1); cp_wait<1>(); }
        else              { cp_wait<0>(); }
        __syncthreads();
        const uint32_t buf = sb + (kt & 1) * KV_STAGE;

        // ---- S = Q K^T  (Q*Kh + Q*Kl) ----
        float s[2][8][4];
#pragma unroll
        for (int f = 0; f < 2; f++)
#pragma unroll
            for (int j = 0; j < 8; j++)
#pragma unroll
                for (int e = 0; e < 4; e++) s[f][j][e] = 0.f;

        const int qg = lane >> 3;
#pragma unroll
        for (int kk = 0; kk < 4; kk++) {
#pragma unroll
            for (int p = 0; p < 4; p++) {
                const uint32_t boff =
                    (uint32_t)((p * 16 + (qg >> 1) * 8 + (lane & 7)) * 144 +
                               (kk * 16 + (qg & 1) * 8) * 2);
                uint32_t B0[2], B1[2], C0[2], C1[2];
                ldsm4(B0[0], B0[1], B1[0], B1[1], buf + boff);
                ldsm4(C0[0], C0[1], C1[0], C1[1], buf + KV_TILE_B + boff);
#pragma unroll
                for (int f = 0; f < 2; f++) {
                    mma_f16(s[f][2 * p],     Qf[kk][f], B0);
                    mma_f16(s[f][2 * p],     Qf[kk][f], C0);
                    mma_f16(s[f][2 * p + 1], Qf[kk][f], B1);
                    mma_f16(s[f][2 * p + 1], Qf[kk][f], C1);
                }
            }
        }

        // ---- causal mask (only near-diagonal tiles) ----
        const int k0 = kt * 64;
        if (k0 + 63 > q0 + w * 32) {
#pragma unroll
            for (int f = 0; f < 2; f++) {
                const int qr0 = q0 + w * 32 + f * 16 + (lane >> 2);
#pragma unroll
                for (int j = 0; j < 8; j++) {
                    const int cb = k0 + j * 8 + (lane & 3) * 2;
#pragma unroll
                    for (int e = 0; e < 4; e++) {
                        const int col = cb + (e & 1);
                        const int qr = qr0 + ((e >> 1) << 3);
                        if (col > qr) s[f][j][e] = -CUDART_INF_F;
                    }
                }
            }
        }

        // ---- online softmax (log2 domain) ----
#pragma unroll
        for (int f = 0; f < 2; f++)
#pragma unroll
        for (int rg = 0; rg < 2; rg++) {
            float mx = s[f][0][rg * 2];
#pragma unroll
            for (int j = 0; j < 8; j++)
                mx = fmaxf(mx, fmaxf(s[f][j][rg * 2], s[f][j][rg * 2 + 1]));
            mx = fmaxf(mx, __shfl_xor_sync(0xffffffffu, mx, 1));
            mx = fmaxf(mx, __shfl_xor_sync(0xffffffffu, mx, 2));
            const float mn = fmaxf(m_[f][rg], mx);
            const float al = ex2(m_[f][rg] - mn);
            float sum = 0.f;
#pragma unroll
            for (int j = 0; j < 8; j++) {
                float p0 = ex2(s[f][j][rg * 2] - mn);
                float p1 = ex2(s[f][j][rg * 2 + 1] - mn);
                s[f][j][rg * 2] = p0; s[f][j][rg * 2 + 1] = p1;
                sum += p0 + p1;
            }
            sum += __shfl_xor_sync(0xffffffffu, sum, 1);
            sum += __shfl_xor_sync(0xffffffffu, sum, 2);
            l_[f][rg] = l_[f][rg] * al + sum;
            m_[f][rg] = mn;
#pragma unroll
            for (int j = 0; j < 8; j++) {
                o[f][j][rg * 2] *= al;
                o[f][j][rg * 2 + 1] *= al;
            }
        }

        // ---- O += P V  (P single fp16; P*Vh + P*Vl) ----
#pragma unroll
        for (int t = 0; t < 4; t++) {
            uint32_t Ph[2][4];
#pragma unroll
            for (int f = 0; f < 2; f++)
#pragma unroll
                for (int idx = 0; idx < 4; idx++)
                    Ph[f][idx] =
                        pack_f16x2(s[f][2 * t + (idx >> 1)][(idx & 1) * 2 + 0],
                                   s[f][2 * t + (idx >> 1)][(idx & 1) * 2 + 1]);
            const int vrow = t * 16 + (lane & 7) + ((lane >> 3) & 1) * 8;
            const int vcb = (lane >> 4) * 8;
#pragma unroll
            for (int u = 0; u < 4; u++) {
                const uint32_t a =
                    buf + 2 * KV_TILE_B + vrow * 144 + (u * 16 + vcb) * 2;
                uint32_t V0[2], V1[2], W0[2], W1[2];
                ldsm4t(V0[0], V0[1], V1[0], V1[1], a);
                ldsm4t(W0[0], W0[1], W1[0], W1[1], a + KV_TILE_B);
#pragma unroll
                for (int f = 0; f < 2; f++) {
                    mma_f16(o[f][2 * u],     Ph[f], V0);
                    mma_f16(o[f][2 * u],     Ph[f], W0);
                    mma_f16(o[f][2 * u + 1], Ph[f], V1);
                    mma_f16(o[f][2 * u + 1], Ph[f], W1);
                }
            }
        }
        __syncthreads();
    }

    // ---- epilogue: normalize, write single fp16 [MTOT][DD] ----
    const int b = bh / HH;
    const int h = bh % HH;
#pragma unroll
    for (int f = 0; f < 2; f++)
#pragma unroll
    for (int rg = 0; rg < 2; rg++) {
        const float inv = 1.0f / l_[f][rg];
        const size_t rbase =
            (size_t)(b * TT + q0 + w * 32 + f * 16 + (lane >> 2) + rg * 8) * DD +
            h * 64;
#pragma unroll
        for (int u = 0; u < 8; u++) {
            const int d0 = u * 8 + (lane & 3) * 2;
            *(__half2*)(ah_ + rbase + d0) =
                __floats2half2_rn(o[f][u][rg * 2] * inv, o[f][u][rg * 2 + 1] * inv);
        }
    }
}

// ---------------------------------------------------------------------------
extern "C" void kernel_launch(void* const* d_in, const int* in_sizes, int n_in,
                              void* d_out, int out_size) {
    const float* x     = (const float*)d_in[0];
    const float* Wqkv  = (const float*)d_in[1];
    const float* Wproj = (const float*)d_in[2];
    const float* bproj = (const float*)d_in[3];
    float* out = (float*)d_out;

    __half *xh, *wh, *wl, *ph, *pl, *ah, *qh, *kh, *kl, *vh, *vl;
    cudaGetSymbolAddress((void**)&xh, g_xh);
    cudaGetSymbolAddress((void**)&wh, g_wh);
    cudaGetSymbolAddress((void**)&wl, g_wl);
    cudaGetSymbolAddress((void**)&ph, g_ph);
    cudaGetSymbolAddress((void**)&pl, g_pl);
    cudaGetSymbolAddress((void**)&ah, g_ah);
    cudaGetSymbolAddress((void**)&qh, g_qh);
    cudaGetSymbolAddress((void**)&kh, g_kh);
    cudaGetSymbolAddress((void**)&kl, g_kl);
    cudaGetSymbolAddress((void**)&vh, g_vh);
    cudaGetSymbolAddress((void**)&vl, g_vl);

    cudaFuncSetAttribute(gemm_mma<0>,
                         cudaFuncAttributeMaxDynamicSharedMemorySize, GEMM_SMEM);
    cudaFuncSetAttribute(gemm_mma<1>,
                         cudaFuncAttributeMaxDynamicSharedMemorySize, GEMM_SMEM);
    cudaFuncSetAttribute(flash_mma,
                         cudaFuncAttributeMaxDynamicSharedMemorySize, FLASH_SMEM);

    // Convert inputs
    {
        int n4 = MTOT * DD / 4;
        split1_kernel<<<(n4 + 255) / 256, 256>>>(x, xh, n4);
        n4 = THREE_D * DD / 4;
        split2_kernel<<<(n4 + 255) / 256, 256>>>(Wqkv, wh, wl, n4);
        n4 = DD * DD / 4;
        split2_kernel<<<(n4 + 255) / 256, 256>>>(Wproj, ph, pl, n4);
    }

    // 1) QKV GEMM -> head-major fp16 q (single, scaled) / k,v (hi/lo)
    {
        dim3 grid(THREE_D / 128, MTOT / 128);
        gemm_mma<1><<<grid, 128, GEMM_SMEM>>>(xh, wh, wl, nullptr, nullptr,
                                              qh, kh, kl, vh, vl,
                                              MTOT, THREE_D, DD);
    }

    // 2) causal flash attention -> ah (single fp16)
    {
        dim3 grid(TT / 128, BB * HH);
        flash_mma<<<grid, 128, FLASH_SMEM>>>(qh, kh, kl, vh, vl, ah);
    }

    // 3) out = attn @ Wproj^T + bproj
    {
        dim3 grid(DD / 128, MTOT / 128);
        gemm_mma<0><<<grid, 128, GEMM_SMEM>>>(ah, ph, pl, out, bproj,
                                              nullptr, nullptr, nullptr,
                                              nullptr, nullptr,
                                              MTOT, DD, DD);
    }
}

// round 15
// speedup vs baseline: 5.0037x; 1.1098x over previous
#include <cuda_runtime.h>
#include <cuda_fp16.h>
#include <math_constants.h>
#include <cstdint>

// R15 = R14 resubmitted unchanged (R14 bench was a broker/container infra
// failure, not a kernel verdict — theory still needs its measurement).

// Problem constants
#define BB 4
#define TT 2048
#define DD 768
#define HH 12
#define DHH 64
#define THREE_D 2304
#define MTOT (BB*TT)       // 8192
#define QSCALE 0.18033688011112042f   // 0.125 * log2(e)

// ---------------------------------------------------------------------------
// Scratch (device globals — no allocation allowed).  fp16 scheme:
// activations single fp16; weights hi/lo; K single; V hi/lo.
// ---------------------------------------------------------------------------
#define QKV_ELEMS ((size_t)BB * HH * TT * DHH)
__device__ __half g_xh[(size_t)MTOT * DD];
__device__ __half g_wh[(size_t)THREE_D * DD];
__device__ __half g_wl[(size_t)THREE_D * DD];
__device__ __half g_ph[(size_t)DD * DD];
__device__ __half g_pl[(size_t)DD * DD];
__device__ __half g_ah[(size_t)MTOT * DD];
__device__ __half g_qh[QKV_ELEMS];
__device__ __half g_kh[QKV_ELEMS];
__device__ __half g_vh[QKV_ELEMS];
__device__ __half g_vl[QKV_ELEMS];

// ---------------------------------------------------------------------------
// PTX helpers (generic sm_80+ only — tcgen05 rejected: harness targets sm_103)
// ---------------------------------------------------------------------------
__device__ __forceinline__ uint32_t smem_u32(const void* p) {
    uint32_t a;
    asm("{ .reg .u64 t; cvta.to.shared.u64 t, %1; cvt.u32.u64 %0, t; }"
        : "=r"(a) : "l"(p));
    return a;
}
__device__ __forceinline__ void cp_async16(uint32_t dst, const void* src) {
    asm volatile("cp.async.cg.shared.global [%0], [%1], 16;"
                 :: "r"(dst), "l"(src));
}
__device__ __forceinline__ void cp_commit() {
    asm volatile("cp.async.commit_group;" ::: "memory");
}
template <int N>
__device__ __forceinline__ void cp_wait() {
    asm volatile("cp.async.wait_group %0;" :: "n"(N) : "memory");
}
__device__ __forceinline__ void ldsm4(uint32_t& r0, uint32_t& r1,
                                      uint32_t& r2, uint32_t& r3, uint32_t a) {
    asm volatile("ldmatrix.sync.aligned.m8n8.x4.shared.b16 {%0,%1,%2,%3}, [%4];"
                 : "=r"(r0), "=r"(r1), "=r"(r2), "=r"(r3) : "r"(a));
}
__device__ __forceinline__ void ldsm4t(uint32_t& r0, uint32_t& r1,
                                       uint32_t& r2, uint32_t& r3, uint32_t a) {
    asm volatile("ldmatrix.sync.aligned.m8n8.x4.trans.shared.b16 {%0,%1,%2,%3}, [%4];"
                 : "=r"(r0), "=r"(r1), "=r"(r2), "=r"(r3) : "r"(a));
}
__device__ __forceinline__ void mma_f16(float* d, const uint32_t* a,
                                        const uint32_t* b) {
    asm volatile(
        "mma.sync.aligned.m16n8k16.row.col.f32.f16.f16.f32 "
        "{%0,%1,%2,%3}, {%4,%5,%6,%7}, {%8,%9}, {%0,%1,%2,%3};"
        : "+f"(d[0]), "+f"(d[1]), "+f"(d[2]), "+f"(d[3])
        : "r"(a[0]), "r"(a[1]), "r"(a[2]), "r"(a[3]), "r"(b[0]), "r"(b[1]));
}
// first elem -> low 16 bits (cvt: first src -> high)
__device__ __forceinline__ uint32_t pack_f16x2(float lo, float hi) {
    uint32_t r;
    asm("cvt.rn.f16x2.f32 %0, %1, %2;" : "=r"(r) : "f"(hi), "f"(lo));
    return r;
}
__device__ __forceinline__ float ex2(float x) {
    float y;
    asm("ex2.approx.ftz.f32 %0, %1;" : "=f"(y) : "f"(x));
    return y;
}
// fp16 hi/lo split store (rn hi + residual re-rounded)
__device__ __forceinline__ void split_store_h(float v0, float v1,
                                              __half* hp, __half* lp) {
    __half2 h = __floats2half2_rn(v0, v1);
    *(__half2*)hp = h;
    float2 f = __half22float2(h);
    *(__half2*)lp = __floats2half2_rn(v0 - f.x, v1 - f.y);
}

// ---------------------------------------------------------------------------
// Conversion kernels
// ---------------------------------------------------------------------------
__global__ __launch_bounds__(256)
void split1_kernel(const float* __restrict__ in, __half* __restrict__ h, int n4) {
    int i = blockIdx.x * blockDim.x + threadIdx.x;
    if (i >= n4) return;
    float4 v = ((const float4*)in)[i];
    ((__half2*)h)[i * 2 + 0] = __floats2half2_rn(v.x, v.y);
    ((__half2*)h)[i * 2 + 1] = __floats2half2_rn(v.z, v.w);
}
__global__ __launch_bounds__(256)
void split2_kernel(const float* __restrict__ in, __half* __restrict__ hi,
                   __half* __restrict__ lo, int n4) {
    int i = blockIdx.x * blockDim.x + threadIdx.x;
    if (i >= n4) return;
    float4 v = ((const float4*)in)[i];
    split_store_h(v.x, v.y, hi + (size_t)i * 4, lo + (size_t)i * 4);
    split_store_h(v.z, v.w, hi + (size_t)i * 4 + 2, lo + (size_t)i * 4 + 2);
}

// ---------------------------------------------------------------------------
// mma.sync GEMM: C[M,N] = A[M,K] @ B[N,K]^T.  A single fp16, B fp16 hi/lo.
// CTA 128x128, 4 warps @ 64x64 (128 threads).  BK=64 (halves barrier count
// vs BK=32), stride 72 halves (144 B) rows, cp.async double-buffered.
// 2 CTAs/SM (2 x 110.6 KB smem <= 228 KB/SM).
// MODE 0: fp32 out + bias.  MODE 1: QKV epilogue -> head-major fp16
//         (q single scaled, k single, v hi/lo).
// ---------------------------------------------------------------------------
#define GTILE_B   (128 * 144)             // 18432 B per tile
#define GBUF_B    (3 * GTILE_B)           // 55296 B per stage
#define GEMM_SMEM (2 * GBUF_B)            // 110592 B

template <int MODE>
__global__ __launch_bounds__(128, 2)
void gemm_mma(const __half* __restrict__ A, const __half* __restrict__ Bh,
              const __half* __restrict__ Bl,
              float* __restrict__ C, const float* __restrict__ bias,
              __half* __restrict__ qh, __half* __restrict__ kh,
              __half* __restrict__ vh, __half* __restrict__ vl,
              int M, int N, int K) {
    extern __shared__ char smem[];
    const uint32_t sb = smem_u32(smem);
    const int tid = threadIdx.x;
    const int lane = tid & 31;
    const int warp = tid >> 5;
    const int wm = warp & 1;       // rows wm*64
    const int wn = warp >> 1;      // cols wn*64
    const int m0 = blockIdx.y * 128;
    const int n0 = blockIdx.x * 128;

    float acc[4][8][4];
#pragma unroll
    for (int f = 0; f < 4; f++)
#pragma unroll
        for (int j = 0; j < 8; j++)
#pragma unroll
            for (int e = 0; e < 4; e++) acc[f][j][e] = 0.f;

    const int nstage = K / 64;

#define ISSUE(s)                                                               \
    do {                                                                       \
        const int k0_ = (s) * 64;                                              \
        const uint32_t db_ = sb + ((s) & 1) * GBUF_B;                          \
        _Pragma("unroll")                                                      \
        for (int i = 0; i < 24; i++) {                                         \
            const int tile = i >> 3;                /* 0=A,1=Bh,2=Bl */        \
            const int cc = tid + (i & 7) * 128;     /* 0..1023 */              \
            const int row = cc >> 3, g = cc & 7;                               \
            const __half* src = (tile == 0) ? A : (tile == 1) ? Bh : Bl;       \
            const int base = (tile == 0) ? m0 : n0;                            \
            cp_async16(db_ + tile * GTILE_B + row * 144 + g * 16,              \
                       src + (size_t)(base + row) * K + k0_ + g * 8);          \
        }                                                                      \
        cp_commit();                                                           \
    } while (0)

    ISSUE(0);

    for (int s = 0; s < nstage; s++) {
        if (s + 1 < nstage) { ISSUE(s + 1); cp_wait<1>(); }
        else                { cp_wait<0>(); }
        __syncthreads();

        const uint32_t bufb = sb + (s & 1) * GBUF_B;
        const int q = lane >> 3;
#pragma unroll
        for (int kk = 0; kk < 64; kk += 16) {
            uint32_t Af[4][4], Bhf[8][2], Blf[8][2];
#pragma unroll
            for (int f = 0; f < 4; f++) {
                uint32_t arow = wm * 64 + f * 16 + (lane & 15);
                uint32_t aoff = arow * 144 + (kk + (lane >> 4) * 8) * 2;
                ldsm4(Af[f][0], Af[f][1], Af[f][2], Af[f][3], bufb + aoff);
            }
#pragma unroll
            for (int p = 0; p < 4; p++) {
                uint32_t brow = wn * 64 + p * 16 + (q >> 1) * 8 + (lane & 7);
                uint32_t boff = brow * 144 + (kk + (q & 1) * 8) * 2;
                ldsm4(Bhf[2 * p][0], Bhf[2 * p][1], Bhf[2 * p + 1][0],
                      Bhf[2 * p + 1][1], bufb + GTILE_B + boff);
                ldsm4(Blf[2 * p][0], Blf[2 * p][1], Blf[2 * p + 1][0],
                      Blf[2 * p + 1][1], bufb + 2 * GTILE_B + boff);
            }
#pragma unroll
            for (int f = 0; f < 4; f++)
#pragma unroll
                for (int j = 0; j < 8; j++) {
                    mma_f16(acc[f][j], Af[f], Bhf[j]);
                    mma_f16(acc[f][j], Af[f], Blf[j]);
                }
        }
        __syncthreads();
    }

    // epilogue
#pragma unroll
    for (int f = 0; f < 4; f++) {
        const int mrow = m0 + wm * 64 + f * 16 + (lane >> 2);
#pragma unroll
        for (int j = 0; j < 8; j++) {
            const int n = n0 + wn * 64 + j * 8 + (lane & 3) * 2;
            if (MODE == 0) {
                float2 v0, v1;
                v0.x = acc[f][j][0]; v0.y = acc[f][j][1];
                v1.x = acc[f][j][2]; v1.y = acc[f][j][3];
                float b0 = bias[n], b1 = bias[n + 1];
                v0.x += b0; v0.y += b1; v1.x += b0; v1.y += b1;
                *(float2*)&C[(size_t)mrow * N + n] = v0;
                *(float2*)&C[(size_t)(mrow + 8) * N + n] = v1;
            } else {
                const int type = n / DD;           // 0=q, 1=k, 2=v
                const int h = (n - type * DD) >> 6;
                const int d = n & 63;
                const int bI = mrow >> 11;
                const int t = mrow & 2047;
                size_t idx = ((size_t)(bI * HH + h) * TT + t) * DHH + d;
                const size_t idx8 = idx + (size_t)8 * DHH;
                if (type == 0) {
                    *(__half2*)(qh + idx) =
                        __floats2half2_rn(acc[f][j][0] * QSCALE, acc[f][j][1] * QSCALE);
                    *(__half2*)(qh + idx8) =
                        __floats2half2_rn(acc[f][j][2] * QSCALE, acc[f][j][3] * QSCALE);
                } else if (type == 1) {
                    *(__half2*)(kh + idx) =
                        __floats2half2_rn(acc[f][j][0], acc[f][j][1]);
                    *(__half2*)(kh + idx8) =
                        __floats2half2_rn(acc[f][j][2], acc[f][j][3]);
                } else {
                    split_store_h(acc[f][j][0], acc[f][j][1], vh + idx, vl + idx);
                    split_store_h(acc[f][j][2], acc[f][j][3], vh + idx8, vl + idx8);
                }
            }
        }
    }
}

// ---------------------------------------------------------------------------
// Causal flash attention, mma.sync fp16.  Q single (regs), K single, V hi/lo.
// BM=128 = 4 warps x 32 rows (128 threads).  BN=64.  Softmax log2 domain.
// Writes attn as single fp16 [MTOT][DD].  2 CTAs/SM.
// ---------------------------------------------------------------------------
#define KV_TILE_B  (64 * 144)             // 64 rows x 144 B (72 halves pad)
#define KV_STAGE   (3 * KV_TILE_B)        // 27648 (kh, vh, vl)
#define FLASH_SMEM (2 * KV_STAGE)         // 55296

__global__ __launch_bounds__(128, 2)
void flash_mma(const __half* __restrict__ qh_, const __half* __restrict__ kh_,
               const __half* __restrict__ vh_, const __half* __restrict__ vl_,
               __half* __restrict__ ah_) {
    extern __shared__ char smem[];
    const uint32_t sb = smem_u32(smem);
    const int tid = threadIdx.x;
    const int lane = tid & 31;
    const int w = tid >> 5;                      // 4 warps, 32 rows each
    const int qt = gridDim.x - 1 - blockIdx.x;   // heavy tiles first
    const int bh = blockIdx.y;
    const int q0 = qt * 128;
    const int nkt = 2 * qt + 2;
    const size_t hbase = (size_t)bh * TT * DHH;

#define FISSUE(s_)                                                             \
    do {                                                                       \
        const int k0_ = (s_) * 64;                                             \
        const uint32_t db_ = sb + ((s_) & 1) * KV_STAGE;                       \
        _Pragma("unroll")                                                      \
        for (int i = 0; i < 12; i++) {                                         \
            const int arr = i >> 2;                 /* 0=kh,1=vh,2=vl */       \
            const int cc = tid + (i & 3) * 128;     /* 0..511 */               \
            const int row = cc >> 3, g = cc & 7;                               \
            const __half* src = (arr == 0) ? kh_ : (arr == 1) ? vh_ : vl_;     \
            cp_async16(db_ + arr * KV_TILE_B + row * 144 + g * 16,             \
                       src + hbase + (size_t)(k0_ + row) * DHH + g * 8);       \
        }                                                                      \
        cp_commit();                                                           \
    } while (0)

    FISSUE(0);

    // Q fragments: 2 m16-tiles x 4 k-steps, single fp16, register resident
    uint32_t Qf[4][2][4];
    {
        const int r = lane >> 2;
        const int c = (lane & 3) * 2;
#pragma unroll
        for (int f = 0; f < 2; f++) {
            const size_t qoff = hbase + (size_t)(q0 + w * 32 + f * 16) * DHH;
#pragma unroll
            for (int kk = 0; kk < 4; kk++) {
                const int cb = c + kk * 16;
                Qf[kk][f][0] = *(const uint32_t*)(qh_ + qoff + r * 64 + cb);
                Qf[kk][f][1] = *(const uint32_t*)(qh_ + qoff + (r + 8) * 64 + cb);
                Qf[kk][f][2] = *(const uint32_t*)(qh_ + qoff + r * 64 + cb + 8);
                Qf[kk][f][3] = *(const uint32_t*)(qh_ + qoff + (r + 8) * 64 + cb + 8);
            }
        }
    }

    float m_[2][2], l_[2][2];
#pragma unroll
    for (int f = 0; f < 2; f++)
#pragma unroll
        for (int rg = 0; rg < 2; rg++) { m_[f][rg] = -CUDART_INF_F; l_[f][rg] = 0.f; }
    float o[2][8][4];
#pragma unroll
    for (int f = 0; f < 2; f++)
#pragma unroll
        for (int j = 0; j < 8; j++)
#pragma unroll
            for (int e = 0; e < 4; e++) o[f][j][e] = 0.f;

    for (int kt = 0; kt < nkt; kt++) {
        if (kt + 1 < nkt) { FISSUE(kt + 1); cp_wait<1>(); }
        else              { cp_wait<0>(); }
        __syncthreads();
        const uint32_t buf = sb + (kt & 1) * KV_STAGE;

        // ---- S = Q K^T  (K single fp16) ----
        float s[2][8][4];
#pragma unroll
        for (int f = 0; f < 2; f++)
#pragma unroll
            for (int j = 0; j < 8; j++)
#pragma unroll
                for (int e = 0; e < 4; e++) s[f][j][e] = 0.f;

        const int qg = lane >> 3;
#pragma unroll
        for (int kk = 0; kk < 4; kk++) {
#pragma unroll
            for (int p = 0; p < 4; p++) {
                const uint32_t boff =
                    (uint32_t)((p * 16 + (qg >> 1) * 8 + (lane & 7)) * 144 +
                               (kk * 16 + (qg & 1) * 8) * 2);
                uint32_t B0[2], B1[2];
                ldsm4(B0[0], B0[1], B1[0], B1[1], buf + boff);
#pragma unroll
                for (int f = 0; f < 2; f++) {
                    mma_f16(s[f][2 * p],     Qf[kk][f], B0);
                    mma_f16(s[f][2 * p + 1], Qf[kk][f], B1);
                }
            }
        }

        // ---- causal mask (only near-diagonal tiles) ----
        const int k0 = kt * 64;
        if (k0 + 63 > q0 + w * 32) {
#pragma unroll
            for (int f = 0; f < 2; f++) {
                const int qr0 = q0 + w * 32 + f * 16 + (lane >> 2);
#pragma unroll
                for (int j = 0; j < 8; j++) {
                    const int cb = k0 + j * 8 + (lane & 3) * 2;
#pragma unroll
                    for (int e = 0; e < 4; e++) {
                        const int col = cb + (e & 1);
                        const int qr = qr0 + ((e >> 1) << 3);
                        if (col > qr) s[f][j][e] = -CUDART_INF_F;
                    }
                }
            }
        }

        // ---- online softmax (log2 domain) ----
#pragma unroll
        for (int f = 0; f < 2; f++)
#pragma unroll
        for (int rg = 0; rg < 2; rg++) {
            float mx = s[f][0][rg * 2];
#pragma unroll
            for (int j = 0; j < 8; j++)
                mx = fmaxf(mx, fmaxf(s[f][j][rg * 2], s[f][j][rg * 2 + 1]));
            mx = fmaxf(mx, __shfl_xor_sync(0xffffffffu, mx, 1));
            mx = fmaxf(mx, __shfl_xor_sync(0xffffffffu, mx, 2));
            const float mn = fmaxf(m_[f][rg], mx);
            const float al = ex2(m_[f][rg] - mn);
            float sum = 0.f;
#pragma unroll
            for (int j = 0; j < 8; j++) {
                float p0 = ex2(s[f][j][rg * 2] - mn);
                float p1 = ex2(s[f][j][rg * 2 + 1] - mn);
                s[f][j][rg * 2] = p0; s[f][j][rg * 2 + 1] = p1;
                sum += p0 + p1;
            }
            sum += __shfl_xor_sync(0xffffffffu, sum, 1);
            sum += __shfl_xor_sync(0xffffffffu, sum, 2);
            l_[f][rg] = l_[f][rg] * al + sum;
            m_[f][rg] = mn;
#pragma unroll
            for (int j = 0; j < 8; j++) {
                o[f][j][rg * 2] *= al;
                o[f][j][rg * 2 + 1] *= al;
            }
        }

        // ---- O += P V  (P single fp16; P*Vh + P*Vl) ----
#pragma unroll
        for (int t = 0; t < 4; t++) {
            uint32_t Ph[2][4];
#pragma unroll
            for (int f = 0; f < 2; f++)
#pragma unroll
                for (int idx = 0; idx < 4; idx++)
                    Ph[f][idx] =
                        pack_f16x2(s[f][2 * t + (idx >> 1)][(idx & 1) * 2 + 0],
                                   s[f][2 * t + (idx >> 1)][(idx & 1) * 2 + 1]);
            const int vrow = t * 16 + (lane & 7) + ((lane >> 3) & 1) * 8;
            const int vcb = (lane >> 4) * 8;
#pragma unroll
            for (int u = 0; u < 4; u++) {
                const uint32_t a =
                    buf + KV_TILE_B + vrow * 144 + (u * 16 + vcb) * 2;
                uint32_t V0[2], V1[2], W0[2], W1[2];
                ldsm4t(V0[0], V0[1], V1[0], V1[1], a);
                ldsm4t(W0[0], W0[1], W1[0], W1[1], a + KV_TILE_B);
#pragma unroll
                for (int f = 0; f < 2; f++) {
                    mma_f16(o[f][2 * u],     Ph[f], V0);
                    mma_f16(o[f][2 * u],     Ph[f], W0);
                    mma_f16(o[f][2 * u + 1], Ph[f], V1);
                    mma_f16(o[f][2 * u + 1], Ph[f], W1);
                }
            }
        }
        __syncthreads();
    }

    // ---- epilogue: normalize, write single fp16 [MTOT][DD] ----
    const int b = bh / HH;
    const int h = bh % HH;
#pragma unroll
    for (int f = 0; f < 2; f++)
#pragma unroll
    for (int rg = 0; rg < 2; rg++) {
        const float inv = 1.0f / l_[f][rg];
        const size_t rbase =
            (size_t)(b * TT + q0 + w * 32 + f * 16 + (lane >> 2) + rg * 8) * DD +
            h * 64;
#pragma unroll
        for (int u = 0; u < 8; u++) {
            const int d0 = u * 8 + (lane & 3) * 2;
            *(__half2*)(ah_ + rbase + d0) =
                __floats2half2_rn(o[f][u][rg * 2] * inv, o[f][u][rg * 2 + 1] * inv);
        }
    }
}

// ---------------------------------------------------------------------------
extern "C" void kernel_launch(void* const* d_in, const int* in_sizes, int n_in,
                              void* d_out, int out_size) {
    const float* x     = (const float*)d_in[0];
    const float* Wqkv  = (const float*)d_in[1];
    const float* Wproj = (const float*)d_in[2];
    const float* bproj = (const float*)d_in[3];
    float* out = (float*)d_out;

    __half *xh, *wh, *wl, *ph, *pl, *ah, *qh, *kh, *vh, *vl;
    cudaGetSymbolAddress((void**)&xh, g_xh);
    cudaGetSymbolAddress((void**)&wh, g_wh);
    cudaGetSymbolAddress((void**)&wl, g_wl);
    cudaGetSymbolAddress((void**)&ph, g_ph);
    cudaGetSymbolAddress((void**)&pl, g_pl);
    cudaGetSymbolAddress((void**)&ah, g_ah);
    cudaGetSymbolAddress((void**)&qh, g_qh);
    cudaGetSymbolAddress((void**)&kh, g_kh);
    cudaGetSymbolAddress((void**)&vh, g_vh);
    cudaGetSymbolAddress((void**)&vl, g_vl);

    cudaFuncSetAttribute(gemm_mma<0>,
                         cudaFuncAttributeMaxDynamicSharedMemorySize, GEMM_SMEM);
    cudaFuncSetAttribute(gemm_mma<1>,
                         cudaFuncAttributeMaxDynamicSharedMemorySize, GEMM_SMEM);
    cudaFuncSetAttribute(flash_mma,
                         cudaFuncAttributeMaxDynamicSharedMemorySize, FLASH_SMEM);

    // Convert inputs
    {
        int n4 = MTOT * DD / 4;
        split1_kernel<<<(n4 + 255) / 256, 256>>>(x, xh, n4);
        n4 = THREE_D * DD / 4;
        split2_kernel<<<(n4 + 255) / 256, 256>>>(Wqkv, wh, wl, n4);
        n4 = DD * DD / 4;
        split2_kernel<<<(n4 + 255) / 256, 256>>>(Wproj, ph, pl, n4);
    }

    // 1) QKV GEMM -> head-major fp16 q (scaled) / k (single) / v (hi/lo)
    {
        dim3 grid(THREE_D / 128, MTOT / 128);
        gemm_mma<1><<<grid, 128, GEMM_SMEM>>>(xh, wh, wl, nullptr, nullptr,
                                              qh, kh, vh, vl,
                                              MTOT, THREE_D, DD);
    }

    // 2) causal flash attention -> ah (single fp16)
    {
        dim3 grid(TT / 128, BB * HH);
        flash_mma<<<grid, 128, FLASH_SMEM>>>(qh, kh, vh, vl, ah);
    }

    // 3) out = attn @ Wproj^T + bproj
    {
        dim3 grid(DD / 128, MTOT / 128);
        gemm_mma<0><<<grid, 128, GEMM_SMEM>>>(ah, ph, pl, out, bproj,
                                              nullptr, nullptr, nullptr, nullptr,
                                              MTOT, DD, DD);
    }
}

// round 16
// speedup vs baseline: 6.7238x; 1.3438x over previous
#include <cuda_runtime.h>
#include <cuda_fp16.h>
#include <math_constants.h>
#include <cstdint>

// Problem constants
#define BB 4
#define TT 2048
#define DD 768
#define HH 12
#define DHH 64
#define THREE_D 2304
#define MTOT (BB*TT)       // 8192
#define QSCALE 0.18033688011112042f   // 0.125 * log2(e)

// ---------------------------------------------------------------------------
// Scratch (device globals — no allocation allowed).  fp16 scheme (R16):
// x, Wqkv, q, k, v, attn all single fp16; ONLY Wproj keeps hi/lo pair.
// ---------------------------------------------------------------------------
#define QKV_ELEMS ((size_t)BB * HH * TT * DHH)
__device__ __half g_xh[(size_t)MTOT * DD];
__device__ __half g_wh[(size_t)THREE_D * DD];
__device__ __half g_ph[(size_t)DD * DD];
__device__ __half g_pl[(size_t)DD * DD];
__device__ __half g_ah[(size_t)MTOT * DD];
__device__ __half g_qh[QKV_ELEMS];
__device__ __half g_kh[QKV_ELEMS];
__device__ __half g_vh[QKV_ELEMS];

// ---------------------------------------------------------------------------
// PTX helpers (generic sm_80+ only — tcgen05 rejected: harness targets sm_103)
// ---------------------------------------------------------------------------
__device__ __forceinline__ uint32_t smem_u32(const void* p) {
    uint32_t a;
    asm("{ .reg .u64 t; cvta.to.shared.u64 t, %1; cvt.u32.u64 %0, t; }"
        : "=r"(a) : "l"(p));
    return a;
}
__device__ __forceinline__ void cp_async16(uint32_t dst, const void* src) {
    asm volatile("cp.async.cg.shared.global [%0], [%1], 16;"
                 :: "r"(dst), "l"(src));
}
__device__ __forceinline__ void cp_commit() {
    asm volatile("cp.async.commit_group;" ::: "memory");
}
template <int N>
__device__ __forceinline__ void cp_wait() {
    asm volatile("cp.async.wait_group %0;" :: "n"(N) : "memory");
}
__device__ __forceinline__ void ldsm4(uint32_t& r0, uint32_t& r1,
                                      uint32_t& r2, uint32_t& r3, uint32_t a) {
    asm volatile("ldmatrix.sync.aligned.m8n8.x4.shared.b16 {%0,%1,%2,%3}, [%4];"
                 : "=r"(r0), "=r"(r1), "=r"(r2), "=r"(r3) : "r"(a));
}
__device__ __forceinline__ void ldsm4t(uint32_t& r0, uint32_t& r1,
                                       uint32_t& r2, uint32_t& r3, uint32_t a) {
    asm volatile("ldmatrix.sync.aligned.m8n8.x4.trans.shared.b16 {%0,%1,%2,%3}, [%4];"
                 : "=r"(r0), "=r"(r1), "=r"(r2), "=r"(r3) : "r"(a));
}
__device__ __forceinline__ void mma_f16(float* d, const uint32_t* a,
                                        const uint32_t* b) {
    asm volatile(
        "mma.sync.aligned.m16n8k16.row.col.f32.f16.f16.f32 "
        "{%0,%1,%2,%3}, {%4,%5,%6,%7}, {%8,%9}, {%0,%1,%2,%3};"
        : "+f"(d[0]), "+f"(d[1]), "+f"(d[2]), "+f"(d[3])
        : "r"(a[0]), "r"(a[1]), "r"(a[2]), "r"(a[3]), "r"(b[0]), "r"(b[1]));
}
// first elem -> low 16 bits (cvt: first src -> high)
__device__ __forceinline__ uint32_t pack_f16x2(float lo, float hi) {
    uint32_t r;
    asm("cvt.rn.f16x2.f32 %0, %1, %2;" : "=r"(r) : "f"(hi), "f"(lo));
    return r;
}
__device__ __forceinline__ float ex2(float x) {
    float y;
    asm("ex2.approx.ftz.f32 %0, %1;" : "=f"(y) : "f"(x));
    return y;
}
// fp16 hi/lo split store (rn hi + residual re-rounded)
__device__ __forceinline__ void split_store_h(float v0, float v1,
                                              __half* hp, __half* lp) {
    __half2 h = __floats2half2_rn(v0, v1);
    *(__half2*)hp = h;
    float2 f = __half22float2(h);
    *(__half2*)lp = __floats2half2_rn(v0 - f.x, v1 - f.y);
}

// ---------------------------------------------------------------------------
// Conversion kernels
// ---------------------------------------------------------------------------
__global__ __launch_bounds__(256)
void split1_kernel(const float* __restrict__ in, __half* __restrict__ h, int n4) {
    int i = blockIdx.x * blockDim.x + threadIdx.x;
    if (i >= n4) return;
    float4 v = ((const float4*)in)[i];
    ((__half2*)h)[i * 2 + 0] = __floats2half2_rn(v.x, v.y);
    ((__half2*)h)[i * 2 + 1] = __floats2half2_rn(v.z, v.w);
}
__global__ __launch_bounds__(256)
void split2_kernel(const float* __restrict__ in, __half* __restrict__ hi,
                   __half* __restrict__ lo, int n4) {
    int i = blockIdx.x * blockDim.x + threadIdx.x;
    if (i >= n4) return;
    float4 v = ((const float4*)in)[i];
    split_store_h(v.x, v.y, hi + (size_t)i * 4, lo + (size_t)i * 4);
    split_store_h(v.z, v.w, hi + (size_t)i * 4 + 2, lo + (size_t)i * 4 + 2);
}

// ---------------------------------------------------------------------------
// mma.sync GEMM: C[M,N] = A[M,K] @ B[N,K]^T.  A single fp16.
// TWOB=1: B is hi/lo pair (2 MMAs/tile; proj).  TWOB=0: B single (QKV).
// CTA 128x128, 4 warps @ 64x64 (128 threads).  BK=64, stride 72 halves
// (144 B) rows, cp.async double-buffered.  2 CTAs/SM.
// MODE 0: fp32 out + bias.  MODE 1: QKV epilogue -> head-major single fp16
//         (q scaled by QSCALE).
// ---------------------------------------------------------------------------
#define GTILE_B   (128 * 144)             // 18432 B per tile

template <int MODE, int TWOB>
__global__ __launch_bounds__(128, 2)
void gemm_mma(const __half* __restrict__ A, const __half* __restrict__ Bh,
              const __half* __restrict__ Bl,
              float* __restrict__ C, const float* __restrict__ bias,
              __half* __restrict__ qh, __half* __restrict__ kh,
              __half* __restrict__ vh, int M, int N, int K) {
    constexpr int NT = 2 + TWOB;                  // tiles per stage
    constexpr uint32_t BUF = NT * GTILE_B;        // stage bytes
    extern __shared__ char smem[];
    const uint32_t sb = smem_u32(smem);
    const int tid = threadIdx.x;
    const int lane = tid & 31;
    const int warp = tid >> 5;
    const int wm = warp & 1;       // rows wm*64
    const int wn = warp >> 1;      // cols wn*64
    const int m0 = blockIdx.y * 128;
    const int n0 = blockIdx.x * 128;

    float acc[4][8][4];
#pragma unroll
    for (int f = 0; f < 4; f++)
#pragma unroll
        for (int j = 0; j < 8; j++)
#pragma unroll
            for (int e = 0; e < 4; e++) acc[f][j][e] = 0.f;

    const int nstage = K / 64;

#define ISSUE(s)                                                               \
    do {                                                                       \
        const int k0_ = (s) * 64;                                              \
        const uint32_t db_ = sb + ((s) & 1) * BUF;                             \
        _Pragma("unroll")                                                      \
        for (int i = 0; i < NT * 8; i++) {                                     \
            const int tile = i >> 3;                /* 0=A,1=Bh,(2=Bl) */      \
            const int cc = tid + (i & 7) * 128;     /* 0..1023 */              \
            const int row = cc >> 3, g = cc & 7;                               \
            const __half* src = (tile == 0) ? A : (tile == 1) ? Bh : Bl;       \
            const int base = (tile == 0) ? m0 : n0;                            \
            cp_async16(db_ + tile * GTILE_B + row * 144 + g * 16,              \
                       src + (size_t)(base + row) * K + k0_ + g * 8);          \
        }                                                                      \
        cp_commit();                                                           \
    } while (0)

    ISSUE(0);

    for (int s = 0; s < nstage; s++) {
        if (s + 1 < nstage) { ISSUE(s + 1); cp_wait<1>(); }
        else                { cp_wait<0>(); }
        __syncthreads();

        const uint32_t bufb = sb + (s & 1) * BUF;
        const int q = lane >> 3;
#pragma unroll
        for (int kk = 0; kk < 64; kk += 16) {
            uint32_t Af[4][4], Bhf[8][2], Blf[8][2];
#pragma unroll
            for (int f = 0; f < 4; f++) {
                uint32_t arow = wm * 64 + f * 16 + (lane & 15);
                uint32_t aoff = arow * 144 + (kk + (lane >> 4) * 8) * 2;
                ldsm4(Af[f][0], Af[f][1], Af[f][2], Af[f][3], bufb + aoff);
            }
#pragma unroll
            for (int p = 0; p < 4; p++) {
                uint32_t brow = wn * 64 + p * 16 + (q >> 1) * 8 + (lane & 7);
                uint32_t boff = brow * 144 + (kk + (q & 1) * 8) * 2;
                ldsm4(Bhf[2 * p][0], Bhf[2 * p][1], Bhf[2 * p + 1][0],
                      Bhf[2 * p + 1][1], bufb + GTILE_B + boff);
                if (TWOB)
                    ldsm4(Blf[2 * p][0], Blf[2 * p][1], Blf[2 * p + 1][0],
                          Blf[2 * p + 1][1], bufb + 2 * GTILE_B + boff);
            }
#pragma unroll
            for (int f = 0; f < 4; f++)
#pragma unroll
                for (int j = 0; j < 8; j++) {
                    mma_f16(acc[f][j], Af[f], Bhf[j]);
                    if (TWOB) mma_f16(acc[f][j], Af[f], Blf[j]);
                }
        }
        __syncthreads();
    }

    // epilogue
#pragma unroll
    for (int f = 0; f < 4; f++) {
        const int mrow = m0 + wm * 64 + f * 16 + (lane >> 2);
#pragma unroll
        for (int j = 0; j < 8; j++) {
            const int n = n0 + wn * 64 + j * 8 + (lane & 3) * 2;
            if (MODE == 0) {
                float2 v0, v1;
                v0.x = acc[f][j][0]; v0.y = acc[f][j][1];
                v1.x = acc[f][j][2]; v1.y = acc[f][j][3];
                float b0 = bias[n], b1 = bias[n + 1];
                v0.x += b0; v0.y += b1; v1.x += b0; v1.y += b1;
                *(float2*)&C[(size_t)mrow * N + n] = v0;
                *(float2*)&C[(size_t)(mrow + 8) * N + n] = v1;
            } else {
                const int type = n / DD;           // 0=q, 1=k, 2=v
                const int h = (n - type * DD) >> 6;
                const int d = n & 63;
                const int bI = mrow >> 11;
                const int t = mrow & 2047;
                size_t idx = ((size_t)(bI * HH + h) * TT + t) * DHH + d;
                const size_t idx8 = idx + (size_t)8 * DHH;
                const float sc = (type == 0) ? QSCALE : 1.0f;
                __half* dst = (type == 0) ? qh : (type == 1) ? kh : vh;
                *(__half2*)(dst + idx) =
                    __floats2half2_rn(acc[f][j][0] * sc, acc[f][j][1] * sc);
                *(__half2*)(dst + idx8) =
                    __floats2half2_rn(acc[f][j][2] * sc, acc[f][j][3] * sc);
            }
        }
    }
}

#define GEMM_SMEM_QKV  (2 * 2 * GTILE_B)   // 73728 (A + B single)
#define GEMM_SMEM_PROJ (2 * 3 * GTILE_B)   // 110592 (A + Bh + Bl)

// ---------------------------------------------------------------------------
// Causal flash attention, mma.sync fp16.  Q single (regs), K single, V single.
// BM=128 = 4 warps x 32 rows (128 threads).  BN=64.  Softmax log2 domain.
// Writes attn as single fp16 [MTOT][DD].  2 CTAs/SM.
// ---------------------------------------------------------------------------
#define KV_TILE_B  (64 * 144)             // 9216 B (64 rows x 72 halves pad)
#define KV_STAGE   (2 * KV_TILE_B)        // 18432 (kh, vh)
#define FLASH_SMEM (2 * KV_STAGE)         // 36864

__global__ __launch_bounds__(128, 2)
void flash_mma(const __half* __restrict__ qh_, const __half* __restrict__ kh_,
               const __half* __restrict__ vh_, __half* __restrict__ ah_) {
    extern __shared__ char smem[];
    const uint32_t sb = smem_u32(smem);
    const int tid = threadIdx.x;
    const int lane = tid & 31;
    const int w = tid >> 5;                      // 4 warps, 32 rows each
    const int qt = gridDim.x - 1 - blockIdx.x;   // heavy tiles first
    const int bh = blockIdx.y;
    const int q0 = qt * 128;
    const int nkt = 2 * qt + 2;
    const size_t hbase = (size_t)bh * TT * DHH;

#define FISSUE(s_)                                                             \
    do {                                                                       \
        const int k0_ = (s_) * 64;                                             \
        const uint32_t db_ = sb + ((s_) & 1) * KV_STAGE;                       \
        _Pragma("unroll")                                                      \
        for (int i = 0; i < 8; i++) {                                          \
            const int arr = i >> 2;                 /* 0=kh,1=vh */            \
            const int cc = tid + (i & 3) * 128;     /* 0..511 */               \
            const int row = cc >> 3, g = cc & 7;                               \
            const __half* src = (arr == 0) ? kh_ : vh_;                        \
            cp_async16(db_ + arr * KV_TILE_B + row * 144 + g * 16,             \
                       src + hbase + (size_t)(k0_ + row) * DHH + g * 8);       \
        }                                                                      \
        cp_commit();                                                           \
    } while (0)

    FISSUE(0);

    // Q fragments: 2 m16-tiles x 4 k-steps, single fp16, register resident
    uint32_t Qf[4][2][4];
    {
        const int r = lane >> 2;
        const int c = (lane & 3) * 2;
#pragma unroll
        for (int f = 0; f < 2; f++) {
            const size_t qoff = hbase + (size_t)(q0 + w * 32 + f * 16) * DHH;
#pragma unroll
            for (int kk = 0; kk < 4; kk++) {
                const int cb = c + kk * 16;
                Qf[kk][f][0] = *(const uint32_t*)(qh_ + qoff + r * 64 + cb);
                Qf[kk][f][1] = *(const uint32_t*)(qh_ + qoff + (r + 8) * 64 + cb);
                Qf[kk][f][2] = *(const uint32_t*)(qh_ + qoff + r * 64 + cb + 8);
                Qf[kk][f][3] = *(const uint32_t*)(qh_ + qoff + (r + 8) * 64 + cb + 8);
            }
        }
    }

    float m_[2][2], l_[2][2];
#pragma unroll
    for (int f = 0; f < 2; f++)
#pragma unroll
        for (int rg = 0; rg < 2; rg++) { m_[f][rg] = -CUDART_INF_F; l_[f][rg] = 0.f; }
    float o[2][8][4];
#pragma unroll
    for (int f = 0; f < 2; f++)
#pragma unroll
        for (int j = 0; j < 8; j++)
#pragma unroll
            for (int e = 0; e < 4; e++) o[f][j][e] = 0.f;

    for (int kt = 0; kt < nkt; kt++) {
        if (kt + 1 < nkt) { FISSUE(kt + 1); cp_wait<1>(); }
        else              { cp_wait<0>(); }
        __syncthreads();
        const uint32_t buf = sb + (kt & 1) * KV_STAGE;

        // ---- S = Q K^T ----
        float s[2][8][4];
#pragma unroll
        for (int f = 0; f < 2; f++)
#pragma unroll
            for (int j = 0; j < 8; j++)
#pragma unroll
                for (int e = 0; e < 4; e++) s[f][j][e] = 0.f;

        const int qg = lane >> 3;
#pragma unroll
        for (int kk = 0; kk < 4; kk++) {
#pragma unroll
            for (int p = 0; p < 4; p++) {
                const uint32_t boff =
                    (uint32_t)((p * 16 + (qg >> 1) * 8 + (lane & 7)) * 144 +
                               (kk * 16 + (qg & 1) * 8) * 2);
                uint32_t B0[2], B1[2];
                ldsm4(B0[0], B0[1], B1[0], B1[1], buf + boff);
#pragma unroll
                for (int f = 0; f < 2; f++) {
                    mma_f16(s[f][2 * p],     Qf[kk][f], B0);
                    mma_f16(s[f][2 * p + 1], Qf[kk][f], B1);
                }
            }
        }

        // ---- causal mask (only near-diagonal tiles) ----
        const int k0 = kt * 64;
        if (k0 + 63 > q0 + w * 32) {
#pragma unroll
            for (int f = 0; f < 2; f++) {
                const int qr0 = q0 + w * 32 + f * 16 + (lane >> 2);
#pragma unroll
                for (int j = 0; j < 8; j++) {
                    const int cb = k0 + j * 8 + (lane & 3) * 2;
#pragma unroll
                    for (int e = 0; e < 4; e++) {
                        const int col = cb + (e & 1);
                        const int qr = qr0 + ((e >> 1) << 3);
                        if (col > qr) s[f][j][e] = -CUDART_INF_F;
                    }
                }
            }
        }

        // ---- online softmax (log2 domain) ----
#pragma unroll
        for (int f = 0; f < 2; f++)
#pragma unroll
        for (int rg = 0; rg < 2; rg++) {
            float mx = s[f][0][rg * 2];
#pragma unroll
            for (int j = 0; j < 8; j++)
                mx = fmaxf(mx, fmaxf(s[f][j][rg * 2], s[f][j][rg * 2 + 1]));
            mx = fmaxf(mx, __shfl_xor_sync(0xffffffffu, mx, 1));
            mx = fmaxf(mx, __shfl_xor_sync(0xffffffffu, mx, 2));
            const float mn = fmaxf(m_[f][rg], mx);
            const float al = ex2(m_[f][rg] - mn);
            float sum = 0.f;
#pragma unroll
            for (int j = 0; j < 8; j++) {
                float p0 = ex2(s[f][j][rg * 2] - mn);
                float p1 = ex2(s[f][j][rg * 2 + 1] - mn);
                s[f][j][rg * 2] = p0; s[f][j][rg * 2 + 1] = p1;
                sum += p0 + p1;
            }
            sum += __shfl_xor_sync(0xffffffffu, sum, 1);
            sum += __shfl_xor_sync(0xffffffffu, sum, 2);
            l_[f][rg] = l_[f][rg] * al + sum;
            m_[f][rg] = mn;
#pragma unroll
            for (int j = 0; j < 8; j++) {
                o[f][j][rg * 2] *= al;
                o[f][j][rg * 2 + 1] *= al;
            }
        }

        // ---- O += P V  (both single fp16) ----
#pragma unroll
        for (int t = 0; t < 4; t++) {
            uint32_t Ph[2][4];
#pragma unroll
            for (int f = 0; f < 2; f++)
#pragma unroll
                for (int idx = 0; idx < 4; idx++)
                    Ph[f][idx] =
                        pack_f16x2(s[f][2 * t + (idx >> 1)][(idx & 1) * 2 + 0],
                                   s[f][2 * t + (idx >> 1)][(idx & 1) * 2 + 1]);
            const int vrow = t * 16 + (lane & 7) + ((lane >> 3) & 1) * 8;
            const int vcb = (lane >> 4) * 8;
#pragma unroll
            for (int u = 0; u < 4; u++) {
                const uint32_t a =
                    buf + KV_TILE_B + vrow * 144 + (u * 16 + vcb) * 2;
                uint32_t V0[2], V1[2];
                ldsm4t(V0[0], V0[1], V1[0], V1[1], a);
#pragma unroll
                for (int f = 0; f < 2; f++) {
                    mma_f16(o[f][2 * u],     Ph[f], V0);
                    mma_f16(o[f][2 * u + 1], Ph[f], V1);
                }
            }
        }
        __syncthreads();
    }

    // ---- epilogue: normalize, write single fp16 [MTOT][DD] ----
    const int b = bh / HH;
    const int h = bh % HH;
#pragma unroll
    for (int f = 0; f < 2; f++)
#pragma unroll
    for (int rg = 0; rg < 2; rg++) {
        const float inv = 1.0f / l_[f][rg];
        const size_t rbase =
            (size_t)(b * TT + q0 + w * 32 + f * 16 + (lane >> 2) + rg * 8) * DD +
            h * 64;
#pragma unroll
        for (int u = 0; u < 8; u++) {
            const int d0 = u * 8 + (lane & 3) * 2;
            *(__half2*)(ah_ + rbase + d0) =
                __floats2half2_rn(o[f][u][rg * 2] * inv, o[f][u][rg * 2 + 1] * inv);
        }
    }
}

// ---------------------------------------------------------------------------
extern "C" void kernel_launch(void* const* d_in, const int* in_sizes, int n_in,
                              void* d_out, int out_size) {
    const float* x     = (const float*)d_in[0];
    const float* Wqkv  = (const float*)d_in[1];
    const float* Wproj = (const float*)d_in[2];
    const float* bproj = (const float*)d_in[3];
    float* out = (float*)d_out;

    __half *xh, *wh, *ph, *pl, *ah, *qh, *kh, *vh;
    cudaGetSymbolAddress((void**)&xh, g_xh);
    cudaGetSymbolAddress((void**)&wh, g_wh);
    cudaGetSymbolAddress((void**)&ph, g_ph);
    cudaGetSymbolAddress((void**)&pl, g_pl);
    cudaGetSymbolAddress((void**)&ah, g_ah);
    cudaGetSymbolAddress((void**)&qh, g_qh);
    cudaGetSymbolAddress((void**)&kh, g_kh);
    cudaGetSymbolAddress((void**)&vh, g_vh);

    cudaFuncSetAttribute((const void*)gemm_mma<1, 0>,
                         cudaFuncAttributeMaxDynamicSharedMemorySize,
                         GEMM_SMEM_QKV);
    cudaFuncSetAttribute((const void*)gemm_mma<0, 1>,
                         cudaFuncAttributeMaxDynamicSharedMemorySize,
                         GEMM_SMEM_PROJ);
    cudaFuncSetAttribute((const void*)flash_mma,
                         cudaFuncAttributeMaxDynamicSharedMemorySize,
                         FLASH_SMEM);

    // Convert inputs
    {
        int n4 = MTOT * DD / 4;
        split1_kernel<<<(n4 + 255) / 256, 256>>>(x, xh, n4);
        n4 = THREE_D * DD / 4;
        split1_kernel<<<(n4 + 255) / 256, 256>>>(Wqkv, wh, n4);
        n4 = DD * DD / 4;
        split2_kernel<<<(n4 + 255) / 256, 256>>>(Wproj, ph, pl, n4);
    }

    // 1) QKV GEMM (single fp16 both sides) -> head-major q (scaled) / k / v
    {
        dim3 grid(THREE_D / 128, MTOT / 128);
        gemm_mma<1, 0><<<grid, 128, GEMM_SMEM_QKV>>>(xh, wh, nullptr,
                                                     nullptr, nullptr,
                                                     qh, kh, vh,
                                                     MTOT, THREE_D, DD);
    }

    // 2) causal flash attention -> ah (single fp16)
    {
        dim3 grid(TT / 128, BB * HH);
        flash_mma<<<grid, 128, FLASH_SMEM>>>(qh, kh, vh, ah);
    }

    // 3) out = attn @ Wproj^T + bproj  (W hi/lo kept for precision)
    {
        dim3 grid(DD / 128, MTOT / 128);
        gemm_mma<0, 1><<<grid, 128, GEMM_SMEM_PROJ>>>(ah, ph, pl, out, bproj,
                                                      nullptr, nullptr, nullptr,
                                                      MTOT, DD, DD);
    }
}